// round 3
// baseline (speedup 1.0000x reference)
#include <cuda_runtime.h>

// Problem constants
#define R_DIM 64
#define C_DIM 256
#define B_DIM 4
#define E_DIM 768
#define Q_DIM 256
#define QD_DIM 512
#define H_DIM 12
#define D_DIM 64
#define M_BIG (R_DIM * C_DIM * B_DIM)   // 65536

// Scratch (device globals; no allocation in kernel_launch)
__device__ float g_xsum[R_DIM * B_DIM * E_DIM];        // [(r*B+n), e]
__device__ float g_qp[Q_DIM * B_DIM * E_DIM];          // [(q*B+n), e]  (already scaled)
__device__ float g_ksum[R_DIM * B_DIM * E_DIM];        // [(r*B+n), e]
__device__ float g_s[R_DIM * B_DIM * H_DIM];           // [(r*B+n)*H + h]
__device__ float g_ctx[M_BIG * E_DIM];                 // 201 MB scratch

// ---------------------------------------------------------------------------
// Kernel 1: xsum[r,n,e] = sum_c x[r,c,n,e]
// grid: (R*B*E)/256 = 768 blocks, 256 threads
// ---------------------------------------------------------------------------
__global__ void xsum_kernel(const float* __restrict__ x, float* __restrict__ xsum)
{
    int o = blockIdx.x * 256 + threadIdx.x;    // 0 .. 196607
    int e = o % E_DIM;
    int rn = o / E_DIM;                        // r*B + n
    int r = rn / B_DIM;
    int n = rn % B_DIM;
    const float* p = x + ((long)(r * C_DIM) * B_DIM + n) * E_DIM + e;
    const long stride = (long)B_DIM * E_DIM;   // 3072
    float a0 = 0.f, a1 = 0.f, a2 = 0.f, a3 = 0.f;
    #pragma unroll 4
    for (int c = 0; c < C_DIM; c += 4) {
        a0 += p[(long)(c + 0) * stride];
        a1 += p[(long)(c + 1) * stride];
        a2 += p[(long)(c + 2) * stride];
        a3 += p[(long)(c + 3) * stride];
    }
    xsum[o] = (a0 + a1) + (a2 + a3);
}

// ---------------------------------------------------------------------------
// Generic tiled SGEMM: out[m, n] = epilogue( sum_k A[m,k] * W[n,k] )
// A: MxK row-major, W: NxK row-major (we multiply by W^T).
// BM=BN=128, BK=16, 256 threads, 8x8 per thread, smem double-buffered.
// EPI=0: out = alpha * (acc + biasScale * bias[n])
// EPI=1: out = (acc + bias[n]) * s[(r*B+n_b)*H + n/64]  (ctx epilogue)
// ---------------------------------------------------------------------------
#define BM 128
#define BN 128
#define BK 16
#define TM 8
#define TN 8
#define BMP (BM + 4)   // pad to 132 floats; keeps float4 alignment (132*4=528=33*16)

template<int EPI>
__global__ __launch_bounds__(256)
void sgemm_kernel(const float* __restrict__ A, const float* __restrict__ W,
                  const float* __restrict__ bias, float* __restrict__ out,
                  int M, int N, int K, float alpha, float biasScale,
                  const float* __restrict__ sArr)
{
    __shared__ __align__(16) float As[2][BK][BMP];
    __shared__ __align__(16) float Bs[2][BK][BMP];

    const int tid = threadIdx.x;
    const int mBase = blockIdx.y * BM;
    const int nBase = blockIdx.x * BN;
    const int tr = tid / 16;          // 0..15
    const int tc = tid % 16;          // 0..15

    const int la_row = tid / 4;       // 0..63
    const int la_q   = (tid % 4) * 4; // 0,4,8,12

    const float* Ag = A + (long)mBase * K;
    const float* Wg = W + (long)nBase * K;

    float acc[TM][TN];
    #pragma unroll
    for (int i = 0; i < TM; i++)
        #pragma unroll
        for (int j = 0; j < TN; j++) acc[i][j] = 0.f;

    float4 ta0, ta1, tb0, tb1;

    // --- prologue: load tile 0 ---
    {
        int kOff = la_q;
        ta0 = *(const float4*)(Ag + (long)la_row * K + kOff);
        ta1 = *(const float4*)(Ag + (long)(la_row + 64) * K + kOff);
        tb0 = *(const float4*)(Wg + (long)la_row * K + kOff);
        tb1 = *(const float4*)(Wg + (long)(la_row + 64) * K + kOff);
        As[0][la_q + 0][la_row] = ta0.x; As[0][la_q + 1][la_row] = ta0.y;
        As[0][la_q + 2][la_row] = ta0.z; As[0][la_q + 3][la_row] = ta0.w;
        As[0][la_q + 0][la_row + 64] = ta1.x; As[0][la_q + 1][la_row + 64] = ta1.y;
        As[0][la_q + 2][la_row + 64] = ta1.z; As[0][la_q + 3][la_row + 64] = ta1.w;
        Bs[0][la_q + 0][la_row] = tb0.x; Bs[0][la_q + 1][la_row] = tb0.y;
        Bs[0][la_q + 2][la_row] = tb0.z; Bs[0][la_q + 3][la_row] = tb0.w;
        Bs[0][la_q + 0][la_row + 64] = tb1.x; Bs[0][la_q + 1][la_row + 64] = tb1.y;
        Bs[0][la_q + 2][la_row + 64] = tb1.z; Bs[0][la_q + 3][la_row + 64] = tb1.w;
    }
    __syncthreads();

    const int KT = K / BK;
    int cur = 0;
    for (int kt = 0; kt < KT; kt++) {
        if (kt + 1 < KT) {
            int kOff = (kt + 1) * BK + la_q;
            ta0 = *(const float4*)(Ag + (long)la_row * K + kOff);
            ta1 = *(const float4*)(Ag + (long)(la_row + 64) * K + kOff);
            tb0 = *(const float4*)(Wg + (long)la_row * K + kOff);
            tb1 = *(const float4*)(Wg + (long)(la_row + 64) * K + kOff);
        }

        #pragma unroll
        for (int kk = 0; kk < BK; kk++) {
            float4 a0 = *(const float4*)&As[cur][kk][tr * TM];
            float4 a1 = *(const float4*)&As[cur][kk][tr * TM + 4];
            float4 b0 = *(const float4*)&Bs[cur][kk][tc * TN];
            float4 b1 = *(const float4*)&Bs[cur][kk][tc * TN + 4];
            float ra[TM] = {a0.x, a0.y, a0.z, a0.w, a1.x, a1.y, a1.z, a1.w};
            float rb[TN] = {b0.x, b0.y, b0.z, b0.w, b1.x, b1.y, b1.z, b1.w};
            #pragma unroll
            for (int i = 0; i < TM; i++)
                #pragma unroll
                for (int j = 0; j < TN; j++)
                    acc[i][j] += ra[i] * rb[j];
        }

        if (kt + 1 < KT) {
            int nb = cur ^ 1;
            As[nb][la_q + 0][la_row] = ta0.x; As[nb][la_q + 1][la_row] = ta0.y;
            As[nb][la_q + 2][la_row] = ta0.z; As[nb][la_q + 3][la_row] = ta0.w;
            As[nb][la_q + 0][la_row + 64] = ta1.x; As[nb][la_q + 1][la_row + 64] = ta1.y;
            As[nb][la_q + 2][la_row + 64] = ta1.z; As[nb][la_q + 3][la_row + 64] = ta1.w;
            Bs[nb][la_q + 0][la_row] = tb0.x; Bs[nb][la_q + 1][la_row] = tb0.y;
            Bs[nb][la_q + 2][la_row] = tb0.z; Bs[nb][la_q + 3][la_row] = tb0.w;
            Bs[nb][la_q + 0][la_row + 64] = tb1.x; Bs[nb][la_q + 1][la_row + 64] = tb1.y;
            Bs[nb][la_q + 2][la_row + 64] = tb1.z; Bs[nb][la_q + 3][la_row + 64] = tb1.w;
            __syncthreads();
            cur ^= 1;
        }
    }

    // --- epilogue ---
    float rbias[TN];
    const int colBase = nBase + tc * TN;
    #pragma unroll
    for (int j = 0; j < TN; j++) rbias[j] = bias[colBase + j];

    #pragma unroll
    for (int i = 0; i < TM; i++) {
        int m = mBase + tr * TM + i;
        float scale;
        if (EPI == 1) {
            int r   = m / (C_DIM * B_DIM);   // m >> 10
            int n_b = m % B_DIM;             // m & 3
            // 8 consecutive cols never cross a 64-wide head boundary
            scale = sArr[(r * B_DIM + n_b) * H_DIM + (colBase >> 6)];
        }
        float v[TN];
        #pragma unroll
        for (int j = 0; j < TN; j++) {
            if (EPI == 0)      v[j] = alpha * (acc[i][j] + biasScale * rbias[j]);
            else               v[j] = (acc[i][j] + rbias[j]) * scale;
        }
        float4* po = (float4*)(out + (long)m * N + colBase);
        po[0] = make_float4(v[0], v[1], v[2], v[3]);
        po[1] = make_float4(v[4], v[5], v[6], v[7]);
    }
}

// ---------------------------------------------------------------------------
// Kernel: attention scores + softmax over r + column-sum over q -> s[h,n,r]
// grid: H*B = 48 blocks, 256 threads (one q per thread)
// ---------------------------------------------------------------------------
__global__ void attn_kernel(const float* __restrict__ qp,
                            const float* __restrict__ ksum,
                            float* __restrict__ sOut)
{
    const int h = blockIdx.x / B_DIM;
    const int n = blockIdx.x % B_DIM;
    const int tid = threadIdx.x;    // q index

    __shared__ float ks[R_DIM][D_DIM + 1];
    __shared__ float sAcc[R_DIM];

    for (int l = tid; l < R_DIM * D_DIM; l += 256) {
        int r = l / D_DIM, d = l % D_DIM;
        ks[r][d] = ksum[(r * B_DIM + n) * E_DIM + h * D_DIM + d];
    }
    if (tid < R_DIM) sAcc[tid] = 0.f;
    __syncthreads();

    // per-thread q vector (already scaled in g_qp)
    float qv[D_DIM];
    const float* qrow = qp + (tid * B_DIM + n) * E_DIM + h * D_DIM;
    #pragma unroll
    for (int d = 0; d < D_DIM; d++) qv[d] = qrow[d];

    float sc[R_DIM];   // may live in local memory; kernel is tiny
    float mx = -1e30f;
    for (int r = 0; r < R_DIM; r++) {
        float a = 0.f;
        #pragma unroll
        for (int d = 0; d < D_DIM; d++) a += qv[d] * ks[r][d];
        sc[r] = a;
        mx = fmaxf(mx, a);
    }
    float sum = 0.f;
    for (int r = 0; r < R_DIM; r++) {
        float e = expf(sc[r] - mx);
        sc[r] = e;
        sum += e;
    }
    float inv = 1.0f / sum;
    for (int r = 0; r < R_DIM; r++)
        atomicAdd(&sAcc[r], sc[r] * inv);
    __syncthreads();

    if (tid < R_DIM)
        sOut[(tid * B_DIM + n) * H_DIM + h] = sAcc[tid];
}

// ---------------------------------------------------------------------------
// Launch
// ---------------------------------------------------------------------------
extern "C" void kernel_launch(void* const* d_in, const int* in_sizes, int n_in,
                              void* d_out, int out_size)
{
    const float* x     = (const float*)d_in[0];
    const float* query = (const float*)d_in[1];
    const float* Wq    = (const float*)d_in[2];
    const float* bq    = (const float*)d_in[3];
    const float* Wk    = (const float*)d_in[4];
    const float* bk    = (const float*)d_in[5];
    const float* Wv    = (const float*)d_in[6];
    const float* bv    = (const float*)d_in[7];
    const float* Wo    = (const float*)d_in[8];
    const float* bo    = (const float*)d_in[9];
    float* out = (float*)d_out;

    void *p_xsum, *p_qp, *p_ksum, *p_s, *p_ctx;
    cudaGetSymbolAddress(&p_xsum, g_xsum);
    cudaGetSymbolAddress(&p_qp,   g_qp);
    cudaGetSymbolAddress(&p_ksum, g_ksum);
    cudaGetSymbolAddress(&p_s,    g_s);
    cudaGetSymbolAddress(&p_ctx,  g_ctx);
    float* xsum = (float*)p_xsum;
    float* qp   = (float*)p_qp;
    float* ksum = (float*)p_ksum;
    float* sArr = (float*)p_s;
    float* ctx  = (float*)p_ctx;

    const float scaling = (1.0f / 8.0f) / 16.0f;   // D^-0.5 / sqrt(Q) = 1/128

    // 1) column-sum of x
    xsum_kernel<<<(R_DIM * B_DIM * E_DIM) / 256, 256>>>(x, xsum);

    // 2) q projection (scaled):  qp = (query @ Wq^T + bq) * scaling
    sgemm_kernel<0><<<dim3(E_DIM / BN, (Q_DIM * B_DIM) / BM), 256>>>(
        query, Wq, bq, qp, Q_DIM * B_DIM, E_DIM, QD_DIM, scaling, 1.0f, nullptr);

    // 3) ksum = xsum @ Wk^T + C*bk
    sgemm_kernel<0><<<dim3(E_DIM / BN, (R_DIM * B_DIM) / BM), 256>>>(
        xsum, Wk, bk, ksum, R_DIM * B_DIM, E_DIM, E_DIM, 1.0f, (float)C_DIM, nullptr);

    // 4) scores + softmax + sum over q -> s[h,n,r]
    attn_kernel<<<H_DIM * B_DIM, 256>>>(qp, ksum, sArr);

    // 5) ctx = s .* (x @ Wv^T + bv)
    sgemm_kernel<1><<<dim3(E_DIM / BN, M_BIG / BM), 256>>>(
        x, Wv, bv, ctx, M_BIG, E_DIM, E_DIM, 1.0f, 1.0f, sArr);

    // 6) out = ctx @ Wo^T + bo
    sgemm_kernel<0><<<dim3(E_DIM / BN, M_BIG / BM), 256>>>(
        ctx, Wo, bo, out, M_BIG, E_DIM, E_DIM, 1.0f, 1.0f, nullptr);
}

// round 4
// speedup vs baseline: 2.1639x; 2.1639x over previous
#include <cuda_runtime.h>
#include <cstdint>

// Problem constants
#define R_DIM 64
#define C_DIM 256
#define B_DIM 4
#define E_DIM 768
#define Q_DIM 256
#define QD_DIM 512
#define H_DIM 12
#define D_DIM 64
#define M_BIG (R_DIM * C_DIM * B_DIM)   // 65536

// Scratch (device globals; no allocation in kernel_launch)
__device__ float g_xsum[R_DIM * B_DIM * E_DIM];
__device__ float g_qp[Q_DIM * B_DIM * E_DIM];
__device__ float g_ksum[R_DIM * B_DIM * E_DIM];
__device__ float g_s[R_DIM * B_DIM * H_DIM];
__device__ float g_ctx[M_BIG * E_DIM];

// ---------------------------------------------------------------------------
// Kernel 1: xsum[r,n,e] = sum_c x[r,c,n,e]
// ---------------------------------------------------------------------------
__global__ void xsum_kernel(const float* __restrict__ x, float* __restrict__ xsum)
{
    int o = blockIdx.x * 256 + threadIdx.x;
    int e = o % E_DIM;
    int rn = o / E_DIM;
    int r = rn / B_DIM;
    int n = rn % B_DIM;
    const float* p = x + ((long)(r * C_DIM) * B_DIM + n) * E_DIM + e;
    const long stride = (long)B_DIM * E_DIM;
    float a0 = 0.f, a1 = 0.f, a2 = 0.f, a3 = 0.f;
    #pragma unroll 4
    for (int c = 0; c < C_DIM; c += 4) {
        a0 += p[(long)(c + 0) * stride];
        a1 += p[(long)(c + 1) * stride];
        a2 += p[(long)(c + 2) * stride];
        a3 += p[(long)(c + 3) * stride];
    }
    xsum[o] = (a0 + a1) + (a2 + a3);
}

// ---------------------------------------------------------------------------
// fp32 SIMT SGEMM (kept for the small, accuracy-critical projections)
// ---------------------------------------------------------------------------
#define BM 128
#define BN 128
#define BK 16
#define TM 8
#define TN 8
#define BMP (BM + 4)

__global__ __launch_bounds__(256)
void sgemm_kernel(const float* __restrict__ A, const float* __restrict__ W,
                  const float* __restrict__ bias, float* __restrict__ out,
                  int M, int N, int K, float alpha, float biasScale)
{
    __shared__ __align__(16) float As[2][BK][BMP];
    __shared__ __align__(16) float Bs[2][BK][BMP];

    const int tid = threadIdx.x;
    const int mBase = blockIdx.y * BM;
    const int nBase = blockIdx.x * BN;
    const int tr = tid / 16;
    const int tc = tid % 16;
    const int la_row = tid / 4;
    const int la_q   = (tid % 4) * 4;

    const float* Ag = A + (long)mBase * K;
    const float* Wg = W + (long)nBase * K;

    float acc[TM][TN];
    #pragma unroll
    for (int i = 0; i < TM; i++)
        #pragma unroll
        for (int j = 0; j < TN; j++) acc[i][j] = 0.f;

    float4 ta0, ta1, tb0, tb1;
    {
        int kOff = la_q;
        ta0 = *(const float4*)(Ag + (long)la_row * K + kOff);
        ta1 = *(const float4*)(Ag + (long)(la_row + 64) * K + kOff);
        tb0 = *(const float4*)(Wg + (long)la_row * K + kOff);
        tb1 = *(const float4*)(Wg + (long)(la_row + 64) * K + kOff);
        As[0][la_q + 0][la_row] = ta0.x; As[0][la_q + 1][la_row] = ta0.y;
        As[0][la_q + 2][la_row] = ta0.z; As[0][la_q + 3][la_row] = ta0.w;
        As[0][la_q + 0][la_row + 64] = ta1.x; As[0][la_q + 1][la_row + 64] = ta1.y;
        As[0][la_q + 2][la_row + 64] = ta1.z; As[0][la_q + 3][la_row + 64] = ta1.w;
        Bs[0][la_q + 0][la_row] = tb0.x; Bs[0][la_q + 1][la_row] = tb0.y;
        Bs[0][la_q + 2][la_row] = tb0.z; Bs[0][la_q + 3][la_row] = tb0.w;
        Bs[0][la_q + 0][la_row + 64] = tb1.x; Bs[0][la_q + 1][la_row + 64] = tb1.y;
        Bs[0][la_q + 2][la_row + 64] = tb1.z; Bs[0][la_q + 3][la_row + 64] = tb1.w;
    }
    __syncthreads();

    const int KT = K / BK;
    int cur = 0;
    for (int kt = 0; kt < KT; kt++) {
        if (kt + 1 < KT) {
            int kOff = (kt + 1) * BK + la_q;
            ta0 = *(const float4*)(Ag + (long)la_row * K + kOff);
            ta1 = *(const float4*)(Ag + (long)(la_row + 64) * K + kOff);
            tb0 = *(const float4*)(Wg + (long)la_row * K + kOff);
            tb1 = *(const float4*)(Wg + (long)(la_row + 64) * K + kOff);
        }
        #pragma unroll
        for (int kk = 0; kk < BK; kk++) {
            float4 a0 = *(const float4*)&As[cur][kk][tr * TM];
            float4 a1 = *(const float4*)&As[cur][kk][tr * TM + 4];
            float4 b0 = *(const float4*)&Bs[cur][kk][tc * TN];
            float4 b1 = *(const float4*)&Bs[cur][kk][tc * TN + 4];
            float ra[TM] = {a0.x, a0.y, a0.z, a0.w, a1.x, a1.y, a1.z, a1.w};
            float rb[TN] = {b0.x, b0.y, b0.z, b0.w, b1.x, b1.y, b1.z, b1.w};
            #pragma unroll
            for (int i = 0; i < TM; i++)
                #pragma unroll
                for (int j = 0; j < TN; j++)
                    acc[i][j] += ra[i] * rb[j];
        }
        if (kt + 1 < KT) {
            int nb = cur ^ 1;
            As[nb][la_q + 0][la_row] = ta0.x; As[nb][la_q + 1][la_row] = ta0.y;
            As[nb][la_q + 2][la_row] = ta0.z; As[nb][la_q + 3][la_row] = ta0.w;
            As[nb][la_q + 0][la_row + 64] = ta1.x; As[nb][la_q + 1][la_row + 64] = ta1.y;
            As[nb][la_q + 2][la_row + 64] = ta1.z; As[nb][la_q + 3][la_row + 64] = ta1.w;
            Bs[nb][la_q + 0][la_row] = tb0.x; Bs[nb][la_q + 1][la_row] = tb0.y;
            Bs[nb][la_q + 2][la_row] = tb0.z; Bs[nb][la_q + 3][la_row] = tb0.w;
            Bs[nb][la_q + 0][la_row + 64] = tb1.x; Bs[nb][la_q + 1][la_row + 64] = tb1.y;
            Bs[nb][la_q + 2][la_row + 64] = tb1.z; Bs[nb][la_q + 3][la_row + 64] = tb1.w;
            __syncthreads();
            cur ^= 1;
        }
    }

    float rbias[TN];
    const int colBase = nBase + tc * TN;
    #pragma unroll
    for (int j = 0; j < TN; j++) rbias[j] = bias[colBase + j];

    #pragma unroll
    for (int i = 0; i < TM; i++) {
        int m = mBase + tr * TM + i;
        float v[TN];
        #pragma unroll
        for (int j = 0; j < TN; j++)
            v[j] = alpha * (acc[i][j] + biasScale * rbias[j]);
        float4* po = (float4*)(out + (long)m * N + colBase);
        po[0] = make_float4(v[0], v[1], v[2], v[3]);
        po[1] = make_float4(v[4], v[5], v[6], v[7]);
    }
}

// ---------------------------------------------------------------------------
// tf32 tensor-core GEMM: out[m,n] = epi( sum_k A[m,k]*W[n,k] )
// 128x128x16 tile, 256 threads, warp tile 64x32 via mma.m16n8k8 tf32.
// Smem layout [row][KP=20] (pad chosen so fragment LDS + float4 STS are
// conflict-free). EPI=0: acc+bias. EPI=1: (acc+bias)*s[(r*B+n_b)*H + col/64].
// ---------------------------------------------------------------------------
#define KP 20

__device__ __forceinline__ float to_tf32(float f) {
    asm("cvt.rna.tf32.f32 %0, %0;" : "+f"(f));
    return f;
}

__device__ __forceinline__ void mma8(float* d, const uint32_t* a, const uint32_t* b) {
    asm volatile(
        "mma.sync.aligned.m16n8k8.row.col.f32.tf32.tf32.f32 "
        "{%0,%1,%2,%3}, {%4,%5,%6,%7}, {%8,%9}, {%0,%1,%2,%3};"
        : "+f"(d[0]), "+f"(d[1]), "+f"(d[2]), "+f"(d[3])
        : "r"(a[0]), "r"(a[1]), "r"(a[2]), "r"(a[3]), "r"(b[0]), "r"(b[1]));
}

template<int EPI>
__global__ __launch_bounds__(256)
void mma_gemm(const float* __restrict__ A, const float* __restrict__ W,
              const float* __restrict__ bias, float* __restrict__ out,
              int M, int N, int K, const float* __restrict__ sArr)
{
    __shared__ __align__(16) float As[2][128 * KP];
    __shared__ __align__(16) float Bs[2][128 * KP];

    const int tid  = threadIdx.x;
    const int w    = tid >> 5;
    const int lane = tid & 31;
    const int wm   = w >> 2;        // 0..1
    const int wn   = w & 3;         // 0..3
    const int lr   = lane >> 2;     // 0..7
    const int lc   = lane & 3;      // 0..3

    const int ldRow = tid >> 1;         // 0..127
    const int ldK   = (tid & 1) * 8;    // 0 or 8

    const float* Ag = A + (size_t)(blockIdx.y * 128 + ldRow) * K + ldK;
    const float* Wg = W + (size_t)(blockIdx.x * 128 + ldRow) * K + ldK;

    float acc[4][4][4];
    #pragma unroll
    for (int i = 0; i < 4; i++)
        #pragma unroll
        for (int j = 0; j < 4; j++)
            #pragma unroll
            for (int t = 0; t < 4; t++) acc[i][j][t] = 0.f;

    float4 ga0, ga1, gb0, gb1;

    // prologue: tile 0
    ga0 = *(const float4*)(Ag);
    ga1 = *(const float4*)(Ag + 4);
    gb0 = *(const float4*)(Wg);
    gb1 = *(const float4*)(Wg + 4);
    {
        float* pa = &As[0][ldRow * KP + ldK];
        float* pb = &Bs[0][ldRow * KP + ldK];
        *(float4*)pa       = make_float4(to_tf32(ga0.x), to_tf32(ga0.y), to_tf32(ga0.z), to_tf32(ga0.w));
        *(float4*)(pa + 4) = make_float4(to_tf32(ga1.x), to_tf32(ga1.y), to_tf32(ga1.z), to_tf32(ga1.w));
        *(float4*)pb       = make_float4(to_tf32(gb0.x), to_tf32(gb0.y), to_tf32(gb0.z), to_tf32(gb0.w));
        *(float4*)(pb + 4) = make_float4(to_tf32(gb1.x), to_tf32(gb1.y), to_tf32(gb1.z), to_tf32(gb1.w));
    }
    __syncthreads();

    const int KT = K / 16;
    int buf = 0;
    for (int kt = 0; kt < KT; kt++) {
        if (kt + 1 < KT) {
            const float* pa = Ag + (kt + 1) * 16;
            const float* pw = Wg + (kt + 1) * 16;
            ga0 = *(const float4*)(pa);
            ga1 = *(const float4*)(pa + 4);
            gb0 = *(const float4*)(pw);
            gb1 = *(const float4*)(pw + 4);
        }

        const float* as = As[buf];
        const float* bs = Bs[buf];
        #pragma unroll
        for (int kk = 0; kk < 16; kk += 8) {
            uint32_t af[4][4], bf[4][2];
            #pragma unroll
            for (int i = 0; i < 4; i++) {
                const float* p = as + (wm * 64 + i * 16 + lr) * KP + kk + lc;
                af[i][0] = __float_as_uint(p[0]);
                af[i][1] = __float_as_uint(p[8 * KP]);
                af[i][2] = __float_as_uint(p[4]);
                af[i][3] = __float_as_uint(p[8 * KP + 4]);
            }
            #pragma unroll
            for (int j = 0; j < 4; j++) {
                const float* p = bs + (wn * 32 + j * 8 + lr) * KP + kk + lc;
                bf[j][0] = __float_as_uint(p[0]);
                bf[j][1] = __float_as_uint(p[4]);
            }
            #pragma unroll
            for (int i = 0; i < 4; i++)
                #pragma unroll
                for (int j = 0; j < 4; j++)
                    mma8(acc[i][j], af[i], bf[j]);
        }

        if (kt + 1 < KT) {
            int nb = buf ^ 1;
            float* pa = &As[nb][ldRow * KP + ldK];
            float* pb = &Bs[nb][ldRow * KP + ldK];
            *(float4*)pa       = make_float4(to_tf32(ga0.x), to_tf32(ga0.y), to_tf32(ga0.z), to_tf32(ga0.w));
            *(float4*)(pa + 4) = make_float4(to_tf32(ga1.x), to_tf32(ga1.y), to_tf32(ga1.z), to_tf32(ga1.w));
            *(float4*)pb       = make_float4(to_tf32(gb0.x), to_tf32(gb0.y), to_tf32(gb0.z), to_tf32(gb0.w));
            *(float4*)(pb + 4) = make_float4(to_tf32(gb1.x), to_tf32(gb1.y), to_tf32(gb1.z), to_tf32(gb1.w));
            __syncthreads();
            buf ^= 1;
        }
    }

    // epilogue
    const int mW = blockIdx.y * 128 + wm * 64;
    const int nW = blockIdx.x * 128 + wn * 32;
    #pragma unroll
    for (int i = 0; i < 4; i++) {
        int row0 = mW + i * 16 + lr;
        int row1 = row0 + 8;
        float s0 = 1.f, s1 = 1.f;
        int rb0 = 0, rb1 = 0;
        if (EPI == 1) {
            rb0 = ((row0 >> 10) * B_DIM + (row0 & 3)) * H_DIM;
            rb1 = ((row1 >> 10) * B_DIM + (row1 & 3)) * H_DIM;
        }
        #pragma unroll
        for (int j = 0; j < 4; j++) {
            int col = nW + j * 8 + lc * 2;
            float b0 = bias[col], b1 = bias[col + 1];
            if (EPI == 1) {
                int head = col >> 6;
                s0 = sArr[rb0 + head];
                s1 = sArr[rb1 + head];
            }
            float v00, v01, v10, v11;
            if (EPI == 0) {
                v00 = acc[i][j][0] + b0; v01 = acc[i][j][1] + b1;
                v10 = acc[i][j][2] + b0; v11 = acc[i][j][3] + b1;
            } else {
                v00 = (acc[i][j][0] + b0) * s0; v01 = (acc[i][j][1] + b1) * s0;
                v10 = (acc[i][j][2] + b0) * s1; v11 = (acc[i][j][3] + b1) * s1;
            }
            *(float2*)(out + (size_t)row0 * N + col) = make_float2(v00, v01);
            *(float2*)(out + (size_t)row1 * N + col) = make_float2(v10, v11);
        }
    }
}

// ---------------------------------------------------------------------------
// Attention: scores + softmax over r + sum over q -> s[(r*B+n)*H + h]
// grid (H*B, Q/64), 256 threads. Warp handles 8 q's; lane owns r=lane, lane+32.
// g_s must be zeroed before launch (accumulated via atomics).
// ---------------------------------------------------------------------------
__global__ void attn_kernel(const float* __restrict__ qp,
                            const float* __restrict__ ksum,
                            float* __restrict__ sOut)
{
    const int h = blockIdx.x / B_DIM;
    const int n = blockIdx.x % B_DIM;
    const int qBase = blockIdx.y * 64;
    const int tid = threadIdx.x;

    __shared__ float ks[R_DIM][D_DIM + 1];
    __shared__ float qs[64][D_DIM + 1];

    for (int l = tid; l < 64 * 64; l += 256) {
        int r = l >> 6, d = l & 63;
        ks[r][d] = ksum[(r * B_DIM + n) * E_DIM + h * D_DIM + d];
        qs[r][d] = qp[((qBase + r) * B_DIM + n) * E_DIM + h * D_DIM + d];
    }
    __syncthreads();

    const int w = tid >> 5, lane = tid & 31;
    float acc0 = 0.f, acc1 = 0.f;
    #pragma unroll 1
    for (int qq = 0; qq < 8; qq++) {
        int q = w * 8 + qq;
        float d0 = 0.f, d1 = 0.f;
        #pragma unroll
        for (int d = 0; d < D_DIM; d++) {
            float qv = qs[q][d];
            d0 += qv * ks[lane][d];
            d1 += qv * ks[lane + 32][d];
        }
        float mx = fmaxf(d0, d1);
        #pragma unroll
        for (int o = 16; o; o >>= 1) mx = fmaxf(mx, __shfl_xor_sync(0xffffffffu, mx, o));
        float e0 = expf(d0 - mx), e1 = expf(d1 - mx);
        float sm = e0 + e1;
        #pragma unroll
        for (int o = 16; o; o >>= 1) sm += __shfl_xor_sync(0xffffffffu, sm, o);
        float inv = 1.f / sm;
        acc0 += e0 * inv;
        acc1 += e1 * inv;
    }
    atomicAdd(&sOut[(lane * B_DIM + n) * H_DIM + h], acc0);
    atomicAdd(&sOut[((lane + 32) * B_DIM + n) * H_DIM + h], acc1);
}

// ---------------------------------------------------------------------------
// Launch
// ---------------------------------------------------------------------------
extern "C" void kernel_launch(void* const* d_in, const int* in_sizes, int n_in,
                              void* d_out, int out_size)
{
    const float* x     = (const float*)d_in[0];
    const float* query = (const float*)d_in[1];
    const float* Wq    = (const float*)d_in[2];
    const float* bq    = (const float*)d_in[3];
    const float* Wk    = (const float*)d_in[4];
    const float* bk    = (const float*)d_in[5];
    const float* Wv    = (const float*)d_in[6];
    const float* bv    = (const float*)d_in[7];
    const float* Wo    = (const float*)d_in[8];
    const float* bo    = (const float*)d_in[9];
    float* out = (float*)d_out;

    void *p_xsum, *p_qp, *p_ksum, *p_s, *p_ctx;
    cudaGetSymbolAddress(&p_xsum, g_xsum);
    cudaGetSymbolAddress(&p_qp,   g_qp);
    cudaGetSymbolAddress(&p_ksum, g_ksum);
    cudaGetSymbolAddress(&p_s,    g_s);
    cudaGetSymbolAddress(&p_ctx,  g_ctx);
    float* xsum = (float*)p_xsum;
    float* qp   = (float*)p_qp;
    float* ksum = (float*)p_ksum;
    float* sArr = (float*)p_s;
    float* ctx  = (float*)p_ctx;

    const float scaling = (1.0f / 8.0f) / 16.0f;   // D^-0.5 / sqrt(Q)

    // zero the attention-sum accumulator (attn uses atomics)
    cudaMemsetAsync(sArr, 0, R_DIM * B_DIM * H_DIM * sizeof(float));

    // 1) column-sum of x
    xsum_kernel<<<(R_DIM * B_DIM * E_DIM) / 256, 256>>>(x, xsum);

    // 2) q projection (scaled), fp32 for accuracy
    sgemm_kernel<<<dim3(E_DIM / BN, (Q_DIM * B_DIM) / BM), 256>>>(
        query, Wq, bq, qp, Q_DIM * B_DIM, E_DIM, QD_DIM, scaling, 1.0f);

    // 3) ksum = xsum @ Wk^T + C*bk, fp32
    sgemm_kernel<<<dim3(E_DIM / BN, (R_DIM * B_DIM) / BM), 256>>>(
        xsum, Wk, bk, ksum, R_DIM * B_DIM, E_DIM, E_DIM, 1.0f, (float)C_DIM);

    // 4) scores + softmax + sum over q -> s
    attn_kernel<<<dim3(H_DIM * B_DIM, Q_DIM / 64), 256>>>(qp, ksum, sArr);

    // 5) ctx = s .* (x @ Wv^T + bv)   [tf32 tensor cores]
    mma_gemm<1><<<dim3(E_DIM / 128, M_BIG / 128), 256>>>(
        x, Wv, bv, ctx, M_BIG, E_DIM, E_DIM, sArr);

    // 6) out = ctx @ Wo^T + bo        [tf32 tensor cores]
    mma_gemm<0><<<dim3(E_DIM / 128, M_BIG / 128), 256>>>(
        ctx, Wo, bo, out, M_BIG, E_DIM, E_DIM, nullptr);
}

// round 5
// speedup vs baseline: 3.3147x; 1.5318x over previous
#include <cuda_runtime.h>
#include <cstdint>

// Problem constants
#define R_DIM 64
#define C_DIM 256
#define B_DIM 4
#define E_DIM 768
#define Q_DIM 256
#define QD_DIM 512
#define H_DIM 12
#define D_DIM 64
#define M_BIG (R_DIM * C_DIM * B_DIM)   // 65536

// Scratch (device globals; no allocation in kernel_launch)
__device__ __align__(16) float g_xsum[R_DIM * B_DIM * E_DIM];
__device__ __align__(16) float g_qp[Q_DIM * B_DIM * E_DIM];
__device__ __align__(16) float g_ksum[R_DIM * B_DIM * E_DIM];
__device__ __align__(16) float g_s[R_DIM * B_DIM * H_DIM];
__device__ __align__(16) float g_ctx[M_BIG * E_DIM];    // tf32-rounded ctx
__device__ __align__(16) float g_rx[M_BIG * E_DIM];     // tf32-rounded x
__device__ __align__(16) float g_rWv[E_DIM * E_DIM];
__device__ __align__(16) float g_rWo[E_DIM * E_DIM];

__device__ __forceinline__ float to_tf32(float f) {
    asm("cvt.rna.tf32.f32 %0, %0;" : "+f"(f));
    return f;
}

// ---------------------------------------------------------------------------
// Kernel 1: xsum[r,n,e] = sum_c x[r,c,n,e]; also writes rx = rna_tf32(x)
// ---------------------------------------------------------------------------
__global__ void xsum_kernel(const float* __restrict__ x,
                            float* __restrict__ xsum,
                            float* __restrict__ rx)
{
    int o = blockIdx.x * 256 + threadIdx.x;
    int e = o % E_DIM;
    int rn = o / E_DIM;
    int r = rn / B_DIM;
    int n = rn % B_DIM;
    const long base = ((long)(r * C_DIM) * B_DIM + n) * E_DIM + e;
    const long stride = (long)B_DIM * E_DIM;
    float a0 = 0.f, a1 = 0.f, a2 = 0.f, a3 = 0.f;
    #pragma unroll 4
    for (int c = 0; c < C_DIM; c += 4) {
        float v0 = x[base + (long)(c + 0) * stride];
        float v1 = x[base + (long)(c + 1) * stride];
        float v2 = x[base + (long)(c + 2) * stride];
        float v3 = x[base + (long)(c + 3) * stride];
        a0 += v0; a1 += v1; a2 += v2; a3 += v3;
        rx[base + (long)(c + 0) * stride] = to_tf32(v0);
        rx[base + (long)(c + 1) * stride] = to_tf32(v1);
        rx[base + (long)(c + 2) * stride] = to_tf32(v2);
        rx[base + (long)(c + 3) * stride] = to_tf32(v3);
    }
    xsum[o] = (a0 + a1) + (a2 + a3);
}

// ---------------------------------------------------------------------------
// Round weights to tf32
// ---------------------------------------------------------------------------
__global__ void roundw_kernel(const float* __restrict__ Wv, const float* __restrict__ Wo,
                              float* __restrict__ rWv, float* __restrict__ rWo)
{
    int i = blockIdx.x * 256 + threadIdx.x;
    rWv[i] = to_tf32(Wv[i]);
    rWo[i] = to_tf32(Wo[i]);
}

// ---------------------------------------------------------------------------
// fp32 SIMT SGEMM (small, accuracy-critical projections)
// ---------------------------------------------------------------------------
#define BM 128
#define BN 128
#define BK 16
#define TM 8
#define TN 8
#define BMP (BM + 4)

__global__ __launch_bounds__(256)
void sgemm_kernel(const float* __restrict__ A, const float* __restrict__ W,
                  const float* __restrict__ bias, float* __restrict__ out,
                  int M, int N, int K, float alpha, float biasScale)
{
    __shared__ __align__(16) float As[2][BK][BMP];
    __shared__ __align__(16) float Bs[2][BK][BMP];

    const int tid = threadIdx.x;
    const int mBase = blockIdx.y * BM;
    const int nBase = blockIdx.x * BN;
    const int tr = tid / 16;
    const int tc = tid % 16;
    const int la_row = tid / 4;
    const int la_q   = (tid % 4) * 4;

    const float* Ag = A + (long)mBase * K;
    const float* Wg = W + (long)nBase * K;

    float acc[TM][TN];
    #pragma unroll
    for (int i = 0; i < TM; i++)
        #pragma unroll
        for (int j = 0; j < TN; j++) acc[i][j] = 0.f;

    float4 ta0, ta1, tb0, tb1;
    {
        int kOff = la_q;
        ta0 = *(const float4*)(Ag + (long)la_row * K + kOff);
        ta1 = *(const float4*)(Ag + (long)(la_row + 64) * K + kOff);
        tb0 = *(const float4*)(Wg + (long)la_row * K + kOff);
        tb1 = *(const float4*)(Wg + (long)(la_row + 64) * K + kOff);
        As[0][la_q + 0][la_row] = ta0.x; As[0][la_q + 1][la_row] = ta0.y;
        As[0][la_q + 2][la_row] = ta0.z; As[0][la_q + 3][la_row] = ta0.w;
        As[0][la_q + 0][la_row + 64] = ta1.x; As[0][la_q + 1][la_row + 64] = ta1.y;
        As[0][la_q + 2][la_row + 64] = ta1.z; As[0][la_q + 3][la_row + 64] = ta1.w;
        Bs[0][la_q + 0][la_row] = tb0.x; Bs[0][la_q + 1][la_row] = tb0.y;
        Bs[0][la_q + 2][la_row] = tb0.z; Bs[0][la_q + 3][la_row] = tb0.w;
        Bs[0][la_q + 0][la_row + 64] = tb1.x; Bs[0][la_q + 1][la_row + 64] = tb1.y;
        Bs[0][la_q + 2][la_row + 64] = tb1.z; Bs[0][la_q + 3][la_row + 64] = tb1.w;
    }
    __syncthreads();

    const int KT = K / BK;
    int cur = 0;
    for (int kt = 0; kt < KT; kt++) {
        if (kt + 1 < KT) {
            int kOff = (kt + 1) * BK + la_q;
            ta0 = *(const float4*)(Ag + (long)la_row * K + kOff);
            ta1 = *(const float4*)(Ag + (long)(la_row + 64) * K + kOff);
            tb0 = *(const float4*)(Wg + (long)la_row * K + kOff);
            tb1 = *(const float4*)(Wg + (long)(la_row + 64) * K + kOff);
        }
        #pragma unroll
        for (int kk = 0; kk < BK; kk++) {
            float4 a0 = *(const float4*)&As[cur][kk][tr * TM];
            float4 a1 = *(const float4*)&As[cur][kk][tr * TM + 4];
            float4 b0 = *(const float4*)&Bs[cur][kk][tc * TN];
            float4 b1 = *(const float4*)&Bs[cur][kk][tc * TN + 4];
            float ra[TM] = {a0.x, a0.y, a0.z, a0.w, a1.x, a1.y, a1.z, a1.w};
            float rb[TN] = {b0.x, b0.y, b0.z, b0.w, b1.x, b1.y, b1.z, b1.w};
            #pragma unroll
            for (int i = 0; i < TM; i++)
                #pragma unroll
                for (int j = 0; j < TN; j++)
                    acc[i][j] += ra[i] * rb[j];
        }
        if (kt + 1 < KT) {
            int nb = cur ^ 1;
            As[nb][la_q + 0][la_row] = ta0.x; As[nb][la_q + 1][la_row] = ta0.y;
            As[nb][la_q + 2][la_row] = ta0.z; As[nb][la_q + 3][la_row] = ta0.w;
            As[nb][la_q + 0][la_row + 64] = ta1.x; As[nb][la_q + 1][la_row + 64] = ta1.y;
            As[nb][la_q + 2][la_row + 64] = ta1.z; As[nb][la_q + 3][la_row + 64] = ta1.w;
            Bs[nb][la_q + 0][la_row] = tb0.x; Bs[nb][la_q + 1][la_row] = tb0.y;
            Bs[nb][la_q + 2][la_row] = tb0.z; Bs[nb][la_q + 3][la_row] = tb0.w;
            Bs[nb][la_q + 0][la_row + 64] = tb1.x; Bs[nb][la_q + 1][la_row + 64] = tb1.y;
            Bs[nb][la_q + 2][la_row + 64] = tb1.z; Bs[nb][la_q + 3][la_row + 64] = tb1.w;
            __syncthreads();
            cur ^= 1;
        }
    }

    float rbias[TN];
    const int colBase = nBase + tc * TN;
    #pragma unroll
    for (int j = 0; j < TN; j++) rbias[j] = bias[colBase + j];

    #pragma unroll
    for (int i = 0; i < TM; i++) {
        int m = mBase + tr * TM + i;
        float v[TN];
        #pragma unroll
        for (int j = 0; j < TN; j++)
            v[j] = alpha * (acc[i][j] + biasScale * rbias[j]);
        float4* po = (float4*)(out + (long)m * N + colBase);
        po[0] = make_float4(v[0], v[1], v[2], v[3]);
        po[1] = make_float4(v[4], v[5], v[6], v[7]);
    }
}

// ---------------------------------------------------------------------------
// tf32 tensor-core GEMM, cp.async 3-stage pipeline, BK=32, 128x128 CTA tile.
// Operands MUST already be tf32-rounded in gmem (cp.async copies raw bytes).
// EPI=0: out = acc + bias[n]
// EPI=1: out = rna_tf32((acc + bias[n]) * s[(r*B+n_b)*H + col/64])
// ---------------------------------------------------------------------------
#define GBK 32
#define GKP 36
#define NSTAGE 3
#define STAGE_F (128 * GKP)
#define GEMM_SMEM_BYTES (2 * NSTAGE * STAGE_F * 4)   // 110592

__device__ __forceinline__ void cp16(void* dst, const void* src) {
    uint32_t d = (uint32_t)__cvta_generic_to_shared(dst);
    asm volatile("cp.async.cg.shared.global [%0], [%1], 16;\n" :: "r"(d), "l"(src));
}

__device__ __forceinline__ void mma8(float* d, const uint32_t* a, const uint32_t* b) {
    asm volatile(
        "mma.sync.aligned.m16n8k8.row.col.f32.tf32.tf32.f32 "
        "{%0,%1,%2,%3}, {%4,%5,%6,%7}, {%8,%9}, {%0,%1,%2,%3};"
        : "+f"(d[0]), "+f"(d[1]), "+f"(d[2]), "+f"(d[3])
        : "r"(a[0]), "r"(a[1]), "r"(a[2]), "r"(a[3]), "r"(b[0]), "r"(b[1]));
}

template<int EPI>
__global__ __launch_bounds__(256)
void mma_gemm(const float* __restrict__ A, const float* __restrict__ W,
              const float* __restrict__ bias, float* __restrict__ out,
              int M, int N, int K, const float* __restrict__ sArr)
{
    extern __shared__ float smf[];
    float* AsBase = smf;
    float* BsBase = smf + NSTAGE * STAGE_F;

    const int tid  = threadIdx.x;
    const int w    = tid >> 5;
    const int lane = tid & 31;
    const int wm   = w >> 2;        // 0..1
    const int wn   = w & 3;         // 0..3
    const int lr   = lane >> 2;     // 0..7
    const int lc   = lane & 3;      // 0..3

    const float* Ag = A + (size_t)(blockIdx.y * 128) * K;
    const float* Wg = W + (size_t)(blockIdx.x * 128) * K;

    float acc[4][4][4];
    #pragma unroll
    for (int i = 0; i < 4; i++)
        #pragma unroll
        for (int j = 0; j < 4; j++)
            #pragma unroll
            for (int t = 0; t < 4; t++) acc[i][j][t] = 0.f;

    const int KT = K / GBK;

    // prologue: stages 0 .. NSTAGE-2
    #pragma unroll
    for (int s = 0; s < NSTAGE - 1; s++) {
        #pragma unroll
        for (int l = 0; l < 4; l++) {
            int f   = l * 256 + tid;
            int row = f >> 3;
            int kq  = (f & 7) * 4;
            cp16(&AsBase[s * STAGE_F + row * GKP + kq], Ag + (size_t)row * K + s * GBK + kq);
            cp16(&BsBase[s * STAGE_F + row * GKP + kq], Wg + (size_t)row * K + s * GBK + kq);
        }
        asm volatile("cp.async.commit_group;\n");
    }

    int sc = 0;               // compute stage
    int sl = NSTAGE - 1;      // load stage
    for (int kt = 0; kt < KT; kt++) {
        asm volatile("cp.async.wait_group %0;\n" :: "n"(NSTAGE - 2) : "memory");
        __syncthreads();

        const float* as = AsBase + sc * STAGE_F;
        const float* bs = BsBase + sc * STAGE_F;
        #pragma unroll
        for (int kc = 0; kc < 4; kc++) {
            const int kk = kc * 8;
            uint32_t af[4][4], bf[4][2];
            #pragma unroll
            for (int i = 0; i < 4; i++) {
                const float* p = as + (wm * 64 + i * 16 + lr) * GKP + kk + lc;
                af[i][0] = __float_as_uint(p[0]);
                af[i][1] = __float_as_uint(p[8 * GKP]);
                af[i][2] = __float_as_uint(p[4]);
                af[i][3] = __float_as_uint(p[8 * GKP + 4]);
            }
            #pragma unroll
            for (int j = 0; j < 4; j++) {
                const float* p = bs + (wn * 32 + j * 8 + lr) * GKP + kk + lc;
                bf[j][0] = __float_as_uint(p[0]);
                bf[j][1] = __float_as_uint(p[4]);
            }
            #pragma unroll
            for (int i = 0; i < 4; i++)
                #pragma unroll
                for (int j = 0; j < 4; j++)
                    mma8(acc[i][j], af[i], bf[j]);
        }

        const int ktNext = kt + NSTAGE - 1;
        if (ktNext < KT) {
            #pragma unroll
            for (int l = 0; l < 4; l++) {
                int f   = l * 256 + tid;
                int row = f >> 3;
                int kq  = (f & 7) * 4;
                cp16(&AsBase[sl * STAGE_F + row * GKP + kq], Ag + (size_t)row * K + ktNext * GBK + kq);
                cp16(&BsBase[sl * STAGE_F + row * GKP + kq], Wg + (size_t)row * K + ktNext * GBK + kq);
            }
        }
        // Always commit (possibly empty group) so wait_group counting stays uniform.
        asm volatile("cp.async.commit_group;\n");

        sc = (sc + 1 == NSTAGE) ? 0 : sc + 1;
        sl = (sl + 1 == NSTAGE) ? 0 : sl + 1;
    }

    // epilogue
    const int mW = blockIdx.y * 128 + wm * 64;
    const int nW = blockIdx.x * 128 + wn * 32;
    #pragma unroll
    for (int i = 0; i < 4; i++) {
        int row0 = mW + i * 16 + lr;
        int row1 = row0 + 8;
        float s0 = 1.f, s1 = 1.f;
        int rb0 = 0, rb1 = 0;
        if (EPI == 1) {
            rb0 = ((row0 >> 10) * B_DIM + (row0 & 3)) * H_DIM;
            rb1 = ((row1 >> 10) * B_DIM + (row1 & 3)) * H_DIM;
        }
        #pragma unroll
        for (int j = 0; j < 4; j++) {
            int col = nW + j * 8 + lc * 2;
            float b0 = bias[col], b1 = bias[col + 1];
            if (EPI == 1) {
                int head = col >> 6;
                s0 = sArr[rb0 + head];
                s1 = sArr[rb1 + head];
            }
            float v00, v01, v10, v11;
            if (EPI == 0) {
                v00 = acc[i][j][0] + b0; v01 = acc[i][j][1] + b1;
                v10 = acc[i][j][2] + b0; v11 = acc[i][j][3] + b1;
            } else {
                v00 = to_tf32((acc[i][j][0] + b0) * s0);
                v01 = to_tf32((acc[i][j][1] + b1) * s0);
                v10 = to_tf32((acc[i][j][2] + b0) * s1);
                v11 = to_tf32((acc[i][j][3] + b1) * s1);
            }
            *(float2*)(out + (size_t)row0 * N + col) = make_float2(v00, v01);
            *(float2*)(out + (size_t)row1 * N + col) = make_float2(v10, v11);
        }
    }
}

// ---------------------------------------------------------------------------
// Attention: scores + softmax over r + sum over q -> s[(r*B+n)*H + h]
// ---------------------------------------------------------------------------
__global__ void attn_kernel(const float* __restrict__ qp,
                            const float* __restrict__ ksum,
                            float* __restrict__ sOut)
{
    const int h = blockIdx.x / B_DIM;
    const int n = blockIdx.x % B_DIM;
    const int qBase = blockIdx.y * 64;
    const int tid = threadIdx.x;

    __shared__ float ks[R_DIM][D_DIM + 1];
    __shared__ float qs[64][D_DIM + 1];

    for (int l = tid; l < 64 * 64; l += 256) {
        int r = l >> 6, d = l & 63;
        ks[r][d] = ksum[(r * B_DIM + n) * E_DIM + h * D_DIM + d];
        qs[r][d] = qp[((qBase + r) * B_DIM + n) * E_DIM + h * D_DIM + d];
    }
    __syncthreads();

    const int w = tid >> 5, lane = tid & 31;
    float acc0 = 0.f, acc1 = 0.f;
    #pragma unroll 1
    for (int qq = 0; qq < 8; qq++) {
        int q = w * 8 + qq;
        float d0 = 0.f, d1 = 0.f;
        #pragma unroll
        for (int d = 0; d < D_DIM; d++) {
            float qv = qs[q][d];
            d0 += qv * ks[lane][d];
            d1 += qv * ks[lane + 32][d];
        }
        float mx = fmaxf(d0, d1);
        #pragma unroll
        for (int o = 16; o; o >>= 1) mx = fmaxf(mx, __shfl_xor_sync(0xffffffffu, mx, o));
        float e0 = expf(d0 - mx), e1 = expf(d1 - mx);
        float sm = e0 + e1;
        #pragma unroll
        for (int o = 16; o; o >>= 1) sm += __shfl_xor_sync(0xffffffffu, sm, o);
        float inv = 1.f / sm;
        acc0 += e0 * inv;
        acc1 += e1 * inv;
    }
    atomicAdd(&sOut[(lane * B_DIM + n) * H_DIM + h], acc0);
    atomicAdd(&sOut[((lane + 32) * B_DIM + n) * H_DIM + h], acc1);
}

// ---------------------------------------------------------------------------
// Launch
// ---------------------------------------------------------------------------
extern "C" void kernel_launch(void* const* d_in, const int* in_sizes, int n_in,
                              void* d_out, int out_size)
{
    const float* x     = (const float*)d_in[0];
    const float* query = (const float*)d_in[1];
    const float* Wq    = (const float*)d_in[2];
    const float* bq    = (const float*)d_in[3];
    const float* Wk    = (const float*)d_in[4];
    const float* bk    = (const float*)d_in[5];
    const float* Wv    = (const float*)d_in[6];
    const float* bv    = (const float*)d_in[7];
    const float* Wo    = (const float*)d_in[8];
    const float* bo    = (const float*)d_in[9];
    float* out = (float*)d_out;

    void *p_xsum, *p_qp, *p_ksum, *p_s, *p_ctx, *p_rx, *p_rWv, *p_rWo;
    cudaGetSymbolAddress(&p_xsum, g_xsum);
    cudaGetSymbolAddress(&p_qp,   g_qp);
    cudaGetSymbolAddress(&p_ksum, g_ksum);
    cudaGetSymbolAddress(&p_s,    g_s);
    cudaGetSymbolAddress(&p_ctx,  g_ctx);
    cudaGetSymbolAddress(&p_rx,   g_rx);
    cudaGetSymbolAddress(&p_rWv,  g_rWv);
    cudaGetSymbolAddress(&p_rWo,  g_rWo);
    float* xsum = (float*)p_xsum;
    float* qp   = (float*)p_qp;
    float* ksum = (float*)p_ksum;
    float* sArr = (float*)p_s;
    float* ctx  = (float*)p_ctx;
    float* rx   = (float*)p_rx;
    float* rWv  = (float*)p_rWv;
    float* rWo  = (float*)p_rWo;

    // raise dynamic smem limit for the pipelined GEMM (host-side, idempotent)
    cudaFuncSetAttribute(mma_gemm<0>, cudaFuncAttributeMaxDynamicSharedMemorySize, GEMM_SMEM_BYTES);
    cudaFuncSetAttribute(mma_gemm<1>, cudaFuncAttributeMaxDynamicSharedMemorySize, GEMM_SMEM_BYTES);

    const float scaling = (1.0f / 8.0f) / 16.0f;   // D^-0.5 / sqrt(Q)

    // zero the attention-sum accumulator (attn uses atomics)
    cudaMemsetAsync(sArr, 0, R_DIM * B_DIM * H_DIM * sizeof(float));

    // 1) column-sum of x + tf32-round x into rx
    xsum_kernel<<<(R_DIM * B_DIM * E_DIM) / 256, 256>>>(x, xsum, rx);

    // 1b) round weights for the tensor-core GEMMs
    roundw_kernel<<<(E_DIM * E_DIM) / 256, 256>>>(Wv, Wo, rWv, rWo);

    // 2) q projection (scaled), fp32
    sgemm_kernel<<<dim3(E_DIM / BN, (Q_DIM * B_DIM) / BM), 256>>>(
        query, Wq, bq, qp, Q_DIM * B_DIM, E_DIM, QD_DIM, scaling, 1.0f);

    // 3) ksum = xsum @ Wk^T + C*bk, fp32
    sgemm_kernel<<<dim3(E_DIM / BN, (R_DIM * B_DIM) / BM), 256>>>(
        xsum, Wk, bk, ksum, R_DIM * B_DIM, E_DIM, E_DIM, 1.0f, (float)C_DIM);

    // 4) scores + softmax + sum over q -> s
    attn_kernel<<<dim3(H_DIM * B_DIM, Q_DIM / 64), 256>>>(qp, ksum, sArr);

    // 5) ctx = rna( s .* (rx @ rWv^T + bv) )   [tf32 tensor cores, cp.async]
    mma_gemm<1><<<dim3(E_DIM / 128, M_BIG / 128), 256, GEMM_SMEM_BYTES>>>(
        rx, rWv, bv, ctx, M_BIG, E_DIM, E_DIM, sArr);

    // 6) out = ctx @ rWo^T + bo               [tf32 tensor cores, cp.async]
    mma_gemm<0><<<dim3(E_DIM / 128, M_BIG / 128), 256, GEMM_SMEM_BYTES>>>(
        ctx, rWo, bo, out, M_BIG, E_DIM, E_DIM, nullptr);
}

// round 11
// speedup vs baseline: 5.4624x; 1.6479x over previous
#include <cuda_runtime.h>
#include <cuda_fp16.h>
#include <cstdint>

// Problem constants
#define R_DIM 64
#define C_DIM 256
#define B_DIM 4
#define E_DIM 768
#define Q_DIM 256
#define QD_DIM 512
#define H_DIM 12
#define D_DIM 64
#define M_BIG (R_DIM * C_DIM * B_DIM)   // 65536

// Scratch (device globals; no allocation in kernel_launch)
__device__ __align__(16) float  g_xsum[R_DIM * B_DIM * E_DIM];
__device__ __align__(16) float  g_qp[Q_DIM * B_DIM * E_DIM];
__device__ __align__(16) float  g_ksum[R_DIM * B_DIM * E_DIM];
__device__ __align__(16) float  g_s[R_DIM * B_DIM * H_DIM];
__device__ __align__(16) __half g_ctx16[M_BIG * E_DIM];   // fp16 ctx
__device__ __align__(16) __half g_x16[M_BIG * E_DIM];     // fp16 x
__device__ __align__(16) __half g_hWv[E_DIM * E_DIM];
__device__ __align__(16) __half g_hWo[E_DIM * E_DIM];

__device__ __forceinline__ uint32_t smem_u32(const void* p) {
    return (uint32_t)__cvta_generic_to_shared(p);
}

// ---------------------------------------------------------------------------
// Kernel 1: xsum[r,n,e] = sum_c x[r,c,n,e]; also writes x16 = fp16(x)
// ---------------------------------------------------------------------------
__global__ void xsum_kernel(const float* __restrict__ x,
                            float* __restrict__ xsum,
                            __half* __restrict__ x16)
{
    int o = blockIdx.x * 256 + threadIdx.x;
    int e = o % E_DIM;
    int rn = o / E_DIM;
    int r = rn / B_DIM;
    int n = rn % B_DIM;
    const long base = ((long)(r * C_DIM) * B_DIM + n) * E_DIM + e;
    const long stride = (long)B_DIM * E_DIM;
    float a0 = 0.f, a1 = 0.f, a2 = 0.f, a3 = 0.f;
    #pragma unroll 4
    for (int c = 0; c < C_DIM; c += 4) {
        float v0 = x[base + (long)(c + 0) * stride];
        float v1 = x[base + (long)(c + 1) * stride];
        float v2 = x[base + (long)(c + 2) * stride];
        float v3 = x[base + (long)(c + 3) * stride];
        a0 += v0; a1 += v1; a2 += v2; a3 += v3;
        x16[base + (long)(c + 0) * stride] = __float2half_rn(v0);
        x16[base + (long)(c + 1) * stride] = __float2half_rn(v1);
        x16[base + (long)(c + 2) * stride] = __float2half_rn(v2);
        x16[base + (long)(c + 3) * stride] = __float2half_rn(v3);
    }
    xsum[o] = (a0 + a1) + (a2 + a3);
}

// ---------------------------------------------------------------------------
// Convert weights to fp16
// ---------------------------------------------------------------------------
__global__ void convw_kernel(const float* __restrict__ Wv, const float* __restrict__ Wo,
                             __half* __restrict__ hWv, __half* __restrict__ hWo)
{
    int i = blockIdx.x * 256 + threadIdx.x;
    hWv[i] = __float2half_rn(Wv[i]);
    hWo[i] = __float2half_rn(Wo[i]);
}

// ---------------------------------------------------------------------------
// fp32 SIMT SGEMM, 64x64 tiles (small accuracy-critical projections)
// ---------------------------------------------------------------------------
__global__ __launch_bounds__(256)
void sgemm64(const float* __restrict__ A, const float* __restrict__ W,
             const float* __restrict__ bias, float* __restrict__ out,
             int M, int N, int K, float alpha, float biasScale)
{
    __shared__ __align__(16) float As[2][16][68];
    __shared__ __align__(16) float Bs[2][16][68];

    const int tid = threadIdx.x;
    const int mBase = blockIdx.y * 64;
    const int nBase = blockIdx.x * 64;
    const int tr = tid >> 4;
    const int tc = tid & 15;
    const int la_row = tid >> 2;
    const int la_q   = (tid & 3) * 4;

    const float* Ar = A + (long)(mBase + la_row) * K;
    const float* Wr = W + (long)(nBase + la_row) * K;

    float acc[4][4];
    #pragma unroll
    for (int i = 0; i < 4; i++)
        #pragma unroll
        for (int j = 0; j < 4; j++) acc[i][j] = 0.f;

    float4 ta, tb;
    ta = *(const float4*)(Ar + la_q);
    tb = *(const float4*)(Wr + la_q);
    As[0][la_q + 0][la_row] = ta.x; As[0][la_q + 1][la_row] = ta.y;
    As[0][la_q + 2][la_row] = ta.z; As[0][la_q + 3][la_row] = ta.w;
    Bs[0][la_q + 0][la_row] = tb.x; Bs[0][la_q + 1][la_row] = tb.y;
    Bs[0][la_q + 2][la_row] = tb.z; Bs[0][la_q + 3][la_row] = tb.w;
    __syncthreads();

    const int KT = K / 16;
    int cur = 0;
    for (int kt = 0; kt < KT; kt++) {
        if (kt + 1 < KT) {
            ta = *(const float4*)(Ar + (kt + 1) * 16 + la_q);
            tb = *(const float4*)(Wr + (kt + 1) * 16 + la_q);
        }
        #pragma unroll
        for (int kk = 0; kk < 16; kk++) {
            float4 a = *(const float4*)&As[cur][kk][tr * 4];
            float4 b = *(const float4*)&Bs[cur][kk][tc * 4];
            float ra[4] = {a.x, a.y, a.z, a.w};
            float rb[4] = {b.x, b.y, b.z, b.w};
            #pragma unroll
            for (int i = 0; i < 4; i++)
                #pragma unroll
                for (int j = 0; j < 4; j++)
                    acc[i][j] += ra[i] * rb[j];
        }
        if (kt + 1 < KT) {
            int nb = cur ^ 1;
            As[nb][la_q + 0][la_row] = ta.x; As[nb][la_q + 1][la_row] = ta.y;
            As[nb][la_q + 2][la_row] = ta.z; As[nb][la_q + 3][la_row] = ta.w;
            Bs[nb][la_q + 0][la_row] = tb.x; Bs[nb][la_q + 1][la_row] = tb.y;
            Bs[nb][la_q + 2][la_row] = tb.z; Bs[nb][la_q + 3][la_row] = tb.w;
            __syncthreads();
            cur ^= 1;
        }
    }

    const int col = nBase + tc * 4;
    float4 bb = *(const float4*)(bias + col);
    float rb4[4] = {bb.x, bb.y, bb.z, bb.w};
    #pragma unroll
    for (int i = 0; i < 4; i++) {
        int m = mBase + tr * 4 + i;
        float4 v;
        v.x = alpha * (acc[i][0] + biasScale * rb4[0]);
        v.y = alpha * (acc[i][1] + biasScale * rb4[1]);
        v.z = alpha * (acc[i][2] + biasScale * rb4[2]);
        v.w = alpha * (acc[i][3] + biasScale * rb4[3]);
        *(float4*)(out + (long)m * N + col) = v;
    }
}

// ---------------------------------------------------------------------------
// fp16 tensor-core GEMM (mma.sync.m16n8k16), cp.async 3-stage ring, BK=32.
// A: MxK fp16 row-major, W: NxK fp16 row-major (computes A @ W^T), fp32 accum.
// EPI=0: out(float) = acc + bias[n]
// EPI=1: out(half)  = fp16((acc + bias[n]) * s[(r*B+n_b)*H + col/64])
// Smem rows: 40 halves (20 words) stride -> conflict-free fragment LDS.
// ---------------------------------------------------------------------------
#define HBK 32                    // K per stage (halves)
#define HLDW 20                   // row stride in 32-bit words (40 halves)
#define HSTG (128 * HLDW)         // stage size in words = 2560 (10240 B)
#define HNST 3
#define HSMEM_BYTES (2 * HNST * HSTG * 4)   // 61440

__device__ __forceinline__ void cp16(void* dst, const void* src) {
    uint32_t d = smem_u32(dst);
    asm volatile("cp.async.cg.shared.global [%0], [%1], 16;\n" :: "r"(d), "l"(src));
}

__device__ __forceinline__ void mma16(float* d, const uint32_t* a, const uint32_t* b) {
    asm volatile(
        "mma.sync.aligned.m16n8k16.row.col.f32.f16.f16.f32 "
        "{%0,%1,%2,%3}, {%4,%5,%6,%7}, {%8,%9}, {%0,%1,%2,%3};"
        : "+f"(d[0]), "+f"(d[1]), "+f"(d[2]), "+f"(d[3])
        : "r"(a[0]), "r"(a[1]), "r"(a[2]), "r"(a[3]), "r"(b[0]), "r"(b[1]));
}

template<int EPI, typename OutT>
__global__ __launch_bounds__(256)
void hmma_gemm(const __half* __restrict__ A, const __half* __restrict__ W,
               const float* __restrict__ bias, OutT* __restrict__ out,
               int M, int N, int K, const float* __restrict__ sArr)
{
    extern __shared__ uint32_t smw[];
    uint32_t* AsBase = smw;
    uint32_t* BsBase = smw + HNST * HSTG;

    const int tid  = threadIdx.x;
    const int w    = tid >> 5;
    const int lane = tid & 31;
    const int wm   = w >> 2;        // 0..1
    const int wn   = w & 3;         // 0..3
    const int lr   = lane >> 2;     // 0..7  (groupID)
    const int lc   = lane & 3;      // 0..3  (threadID in group)

    // cp.async mapping: 2 chunks of 16B per thread per matrix per stage
    // f = l*256 + tid; row = f>>2 (0..127), q = f&3 (16B chunk = 8 halves)
    const __half* Ag = A + (size_t)(blockIdx.y * 128) * K;
    const __half* Wg = W + (size_t)(blockIdx.x * 128) * K;

    float acc[4][4][4];
    #pragma unroll
    for (int i = 0; i < 4; i++)
        #pragma unroll
        for (int j = 0; j < 4; j++)
            #pragma unroll
            for (int t = 0; t < 4; t++) acc[i][j][t] = 0.f;

    const int KT = K / HBK;   // 24

    // prologue
    #pragma unroll
    for (int s = 0; s < HNST - 1; s++) {
        #pragma unroll
        for (int l = 0; l < 2; l++) {
            int f = l * 256 + tid;
            int row = f >> 2;
            int q = f & 3;
            cp16(&AsBase[s * HSTG + row * HLDW + q * 4], Ag + (size_t)row * K + s * HBK + q * 8);
            cp16(&BsBase[s * HSTG + row * HLDW + q * 4], Wg + (size_t)row * K + s * HBK + q * 8);
        }
        asm volatile("cp.async.commit_group;\n");
    }

    int sc = 0, sl = HNST - 1;
    for (int kt = 0; kt < KT; kt++) {
        asm volatile("cp.async.wait_group %0;\n" :: "n"(HNST - 2) : "memory");
        __syncthreads();

        const uint32_t* as = AsBase + sc * HSTG;
        const uint32_t* bs = BsBase + sc * HSTG;
        #pragma unroll
        for (int kc = 0; kc < 2; kc++) {
            const int kw = kc * 8;   // k16 chunk base, in words
            uint32_t af[4][4], bf[4][2];
            #pragma unroll
            for (int i = 0; i < 4; i++) {
                const uint32_t* p = as + (wm * 64 + i * 16 + lr) * HLDW + kw + lc;
                af[i][0] = p[0];             // (row g,   cols 2lc,2lc+1)
                af[i][1] = p[8 * HLDW];      // (row g+8, cols 2lc)
                af[i][2] = p[4];             // (row g,   cols 2lc+8)
                af[i][3] = p[8 * HLDW + 4];  // (row g+8, cols 2lc+8)
            }
            #pragma unroll
            for (int j = 0; j < 4; j++) {
                const uint32_t* p = bs + (wn * 32 + j * 8 + lr) * HLDW + kw + lc;
                bf[j][0] = p[0];             // (rows 2lc, col g)
                bf[j][1] = p[4];             // (rows 2lc+8, col g)
            }
            #pragma unroll
            for (int i = 0; i < 4; i++)
                #pragma unroll
                for (int j = 0; j < 4; j++)
                    mma16(acc[i][j], af[i], bf[j]);
        }

        const int ktNext = kt + HNST - 1;
        if (ktNext < KT) {
            #pragma unroll
            for (int l = 0; l < 2; l++) {
                int f = l * 256 + tid;
                int row = f >> 2;
                int q = f & 3;
                cp16(&AsBase[sl * HSTG + row * HLDW + q * 4],
                     Ag + (size_t)row * K + ktNext * HBK + q * 8);
                cp16(&BsBase[sl * HSTG + row * HLDW + q * 4],
                     Wg + (size_t)row * K + ktNext * HBK + q * 8);
            }
        }
        asm volatile("cp.async.commit_group;\n");

        sc = (sc + 1 == HNST) ? 0 : sc + 1;
        sl = (sl + 1 == HNST) ? 0 : sl + 1;
    }

    // epilogue (accumulator layout: rows lr, lr+8; cols 2lc, 2lc+1)
    const int mW = blockIdx.y * 128 + wm * 64;
    const int nW = blockIdx.x * 128 + wn * 32;
    #pragma unroll
    for (int i = 0; i < 4; i++) {
        int row0 = mW + i * 16 + lr;
        int row1 = row0 + 8;
        float s0 = 1.f, s1 = 1.f;
        int rb0 = 0, rb1 = 0;
        if (EPI == 1) {
            rb0 = ((row0 >> 10) * B_DIM + (row0 & 3)) * H_DIM;
            rb1 = ((row1 >> 10) * B_DIM + (row1 & 3)) * H_DIM;
        }
        #pragma unroll
        for (int j = 0; j < 4; j++) {
            int col = nW + j * 8 + lc * 2;
            float b0 = bias[col], b1 = bias[col + 1];
            if (EPI == 1) {
                int head = col >> 6;
                s0 = sArr[rb0 + head];
                s1 = sArr[rb1 + head];
            }
            if (EPI == 0) {
                float v00 = acc[i][j][0] + b0, v01 = acc[i][j][1] + b1;
                float v10 = acc[i][j][2] + b0, v11 = acc[i][j][3] + b1;
                *(float2*)((float*)out + (size_t)row0 * N + col) = make_float2(v00, v01);
                *(float2*)((float*)out + (size_t)row1 * N + col) = make_float2(v10, v11);
            } else {
                __half2 h0 = __floats2half2_rn((acc[i][j][0] + b0) * s0,
                                               (acc[i][j][1] + b1) * s0);
                __half2 h1 = __floats2half2_rn((acc[i][j][2] + b0) * s1,
                                               (acc[i][j][3] + b1) * s1);
                *(__half2*)((__half*)out + (size_t)row0 * N + col) = h0;
                *(__half2*)((__half*)out + (size_t)row1 * N + col) = h1;
            }
        }
    }
}

// ---------------------------------------------------------------------------
// Attention: scores + softmax over r + sum over q -> s[(r*B+n)*H + h]
// ---------------------------------------------------------------------------
__global__ void attn_kernel(const float* __restrict__ qp,
                            const float* __restrict__ ksum,
                            float* __restrict__ sOut)
{
    const int h = blockIdx.x / B_DIM;
    const int n = blockIdx.x % B_DIM;
    const int qBase = blockIdx.y * 64;
    const int tid = threadIdx.x;

    __shared__ float ks[R_DIM][D_DIM + 1];
    __shared__ float qs[64][D_DIM + 1];

    for (int l = tid; l < 64 * 64; l += 256) {
        int r = l >> 6, d = l & 63;
        ks[r][d] = ksum[(r * B_DIM + n) * E_DIM + h * D_DIM + d];
        qs[r][d] = qp[((qBase + r) * B_DIM + n) * E_DIM + h * D_DIM + d];
    }
    __syncthreads();

    const int w = tid >> 5, lane = tid & 31;
    float acc0 = 0.f, acc1 = 0.f;
    #pragma unroll 1
    for (int qq = 0; qq < 8; qq++) {
        int q = w * 8 + qq;
        float d0 = 0.f, d1 = 0.f;
        #pragma unroll
        for (int d = 0; d < D_DIM; d++) {
            float qv = qs[q][d];
            d0 += qv * ks[lane][d];
            d1 += qv * ks[lane + 32][d];
        }
        float mx = fmaxf(d0, d1);
        #pragma unroll
        for (int o = 16; o; o >>= 1) mx = fmaxf(mx, __shfl_xor_sync(0xffffffffu, mx, o));
        float e0 = expf(d0 - mx), e1 = expf(d1 - mx);
        float sm = e0 + e1;
        #pragma unroll
        for (int o = 16; o; o >>= 1) sm += __shfl_xor_sync(0xffffffffu, sm, o);
        float inv = 1.f / sm;
        acc0 += e0 * inv;
        acc1 += e1 * inv;
    }
    atomicAdd(&sOut[(lane * B_DIM + n) * H_DIM + h], acc0);
    atomicAdd(&sOut[((lane + 32) * B_DIM + n) * H_DIM + h], acc1);
}

// ---------------------------------------------------------------------------
// Launch
// ---------------------------------------------------------------------------
extern "C" void kernel_launch(void* const* d_in, const int* in_sizes, int n_in,
                              void* d_out, int out_size)
{
    const float* x     = (const float*)d_in[0];
    const float* query = (const float*)d_in[1];
    const float* Wq    = (const float*)d_in[2];
    const float* bq    = (const float*)d_in[3];
    const float* Wk    = (const float*)d_in[4];
    const float* bk    = (const float*)d_in[5];
    const float* Wv    = (const float*)d_in[6];
    const float* bv    = (const float*)d_in[7];
    const float* Wo    = (const float*)d_in[8];
    const float* bo    = (const float*)d_in[9];
    float* out = (float*)d_out;

    void *p_xsum, *p_qp, *p_ksum, *p_s, *p_ctx, *p_x16, *p_hWv, *p_hWo;
    cudaGetSymbolAddress(&p_xsum, g_xsum);
    cudaGetSymbolAddress(&p_qp,   g_qp);
    cudaGetSymbolAddress(&p_ksum, g_ksum);
    cudaGetSymbolAddress(&p_s,    g_s);
    cudaGetSymbolAddress(&p_ctx,  g_ctx16);
    cudaGetSymbolAddress(&p_x16,  g_x16);
    cudaGetSymbolAddress(&p_hWv,  g_hWv);
    cudaGetSymbolAddress(&p_hWo,  g_hWo);
    float*  xsum = (float*)p_xsum;
    float*  qp   = (float*)p_qp;
    float*  ksum = (float*)p_ksum;
    float*  sArr = (float*)p_s;
    __half* ctx  = (__half*)p_ctx;
    __half* x16  = (__half*)p_x16;
    __half* hWv  = (__half*)p_hWv;
    __half* hWo  = (__half*)p_hWo;

    cudaFuncSetAttribute(hmma_gemm<0, float>,
                         cudaFuncAttributeMaxDynamicSharedMemorySize, HSMEM_BYTES);
    cudaFuncSetAttribute(hmma_gemm<1, __half>,
                         cudaFuncAttributeMaxDynamicSharedMemorySize, HSMEM_BYTES);

    const float scaling = (1.0f / 8.0f) / 16.0f;   // D^-0.5 / sqrt(Q)

    cudaMemsetAsync(sArr, 0, R_DIM * B_DIM * H_DIM * sizeof(float));

    // 1) column-sum of x + fp16 conversion
    xsum_kernel<<<(R_DIM * B_DIM * E_DIM) / 256, 256>>>(x, xsum, x16);

    // 1b) convert weights to fp16
    convw_kernel<<<(E_DIM * E_DIM) / 256, 256>>>(Wv, Wo, hWv, hWo);

    // 2) q projection (scaled), fp32
    sgemm64<<<dim3(E_DIM / 64, (Q_DIM * B_DIM) / 64), 256>>>(
        query, Wq, bq, qp, Q_DIM * B_DIM, E_DIM, QD_DIM, scaling, 1.0f);

    // 3) ksum = xsum @ Wk^T + C*bk, fp32
    sgemm64<<<dim3(E_DIM / 64, (R_DIM * B_DIM) / 64), 256>>>(
        xsum, Wk, bk, ksum, R_DIM * B_DIM, E_DIM, E_DIM, 1.0f, (float)C_DIM);

    // 4) scores + softmax + sum over q -> s
    attn_kernel<<<dim3(H_DIM * B_DIM, Q_DIM / 64), 256>>>(qp, ksum, sArr);

    // 5) ctx = fp16( s .* (x16 @ hWv^T + bv) )   [fp16 tensor cores]
    hmma_gemm<1, __half><<<dim3(E_DIM / 128, M_BIG / 128), 256, HSMEM_BYTES>>>(
        x16, hWv, bv, ctx, M_BIG, E_DIM, E_DIM, sArr);

    // 6) out = ctx @ hWo^T + bo                  [fp16 tensor cores]
    hmma_gemm<0, float><<<dim3(E_DIM / 128, M_BIG / 128), 256, HSMEM_BYTES>>>(
        ctx, hWo, bo, out, M_BIG, E_DIM, E_DIM, nullptr);
}

// round 12
// speedup vs baseline: 5.4978x; 1.0065x over previous
#include <cuda_runtime.h>
#include <cuda_fp16.h>
#include <cstdint>

// Problem constants
#define R_DIM 64
#define C_DIM 256
#define B_DIM 4
#define E_DIM 768
#define Q_DIM 256
#define QD_DIM 512
#define H_DIM 12
#define D_DIM 64
#define M_BIG (R_DIM * C_DIM * B_DIM)   // 65536

// Scratch (device globals; no allocation in kernel_launch)
__device__ __align__(16) float  g_xsum[R_DIM * B_DIM * E_DIM];
__device__ __align__(16) float  g_qp[Q_DIM * B_DIM * E_DIM];
__device__ __align__(16) float  g_ksum[R_DIM * B_DIM * E_DIM];
__device__ __align__(16) float  g_s[R_DIM * B_DIM * H_DIM];
__device__ __align__(16) __half g_ctx16[M_BIG * E_DIM];   // fp16 ctx
__device__ __align__(16) __half g_x16[M_BIG * E_DIM];     // fp16 x
__device__ __align__(16) __half g_hWv[E_DIM * E_DIM];
__device__ __align__(16) __half g_hWo[E_DIM * E_DIM];

__device__ __forceinline__ uint32_t smem_u32(const void* p) {
    return (uint32_t)__cvta_generic_to_shared(p);
}

// ---------------------------------------------------------------------------
// Kernel 1: xsum[r,n,e] = sum_c x[r,c,n,e]; also writes x16 = fp16(x)
// ---------------------------------------------------------------------------
__global__ void xsum_kernel(const float* __restrict__ x,
                            float* __restrict__ xsum,
                            __half* __restrict__ x16)
{
    int o = blockIdx.x * 256 + threadIdx.x;
    int e = o % E_DIM;
    int rn = o / E_DIM;
    int r = rn / B_DIM;
    int n = rn % B_DIM;
    const long base = ((long)(r * C_DIM) * B_DIM + n) * E_DIM + e;
    const long stride = (long)B_DIM * E_DIM;
    float a0 = 0.f, a1 = 0.f, a2 = 0.f, a3 = 0.f;
    #pragma unroll 4
    for (int c = 0; c < C_DIM; c += 4) {
        float v0 = x[base + (long)(c + 0) * stride];
        float v1 = x[base + (long)(c + 1) * stride];
        float v2 = x[base + (long)(c + 2) * stride];
        float v3 = x[base + (long)(c + 3) * stride];
        a0 += v0; a1 += v1; a2 += v2; a3 += v3;
        x16[base + (long)(c + 0) * stride] = __float2half_rn(v0);
        x16[base + (long)(c + 1) * stride] = __float2half_rn(v1);
        x16[base + (long)(c + 2) * stride] = __float2half_rn(v2);
        x16[base + (long)(c + 3) * stride] = __float2half_rn(v3);
    }
    xsum[o] = (a0 + a1) + (a2 + a3);
}

// ---------------------------------------------------------------------------
// Convert weights to fp16
// ---------------------------------------------------------------------------
__global__ void convw_kernel(const float* __restrict__ Wv, const float* __restrict__ Wo,
                             __half* __restrict__ hWv, __half* __restrict__ hWo)
{
    int i = blockIdx.x * 256 + threadIdx.x;
    hWv[i] = __float2half_rn(Wv[i]);
    hWo[i] = __float2half_rn(Wo[i]);
}

// ---------------------------------------------------------------------------
// fp32 SIMT SGEMM, 64x64 tiles (small accuracy-critical projections)
// ---------------------------------------------------------------------------
__global__ __launch_bounds__(256)
void sgemm64(const float* __restrict__ A, const float* __restrict__ W,
             const float* __restrict__ bias, float* __restrict__ out,
             int M, int N, int K, float alpha, float biasScale)
{
    __shared__ __align__(16) float As[2][16][68];
    __shared__ __align__(16) float Bs[2][16][68];

    const int tid = threadIdx.x;
    const int mBase = blockIdx.y * 64;
    const int nBase = blockIdx.x * 64;
    const int tr = tid >> 4;
    const int tc = tid & 15;
    const int la_row = tid >> 2;
    const int la_q   = (tid & 3) * 4;

    const float* Ar = A + (long)(mBase + la_row) * K;
    const float* Wr = W + (long)(nBase + la_row) * K;

    float acc[4][4];
    #pragma unroll
    for (int i = 0; i < 4; i++)
        #pragma unroll
        for (int j = 0; j < 4; j++) acc[i][j] = 0.f;

    float4 ta, tb;
    ta = *(const float4*)(Ar + la_q);
    tb = *(const float4*)(Wr + la_q);
    As[0][la_q + 0][la_row] = ta.x; As[0][la_q + 1][la_row] = ta.y;
    As[0][la_q + 2][la_row] = ta.z; As[0][la_q + 3][la_row] = ta.w;
    Bs[0][la_q + 0][la_row] = tb.x; Bs[0][la_q + 1][la_row] = tb.y;
    Bs[0][la_q + 2][la_row] = tb.z; Bs[0][la_q + 3][la_row] = tb.w;
    __syncthreads();

    const int KT = K / 16;
    int cur = 0;
    for (int kt = 0; kt < KT; kt++) {
        if (kt + 1 < KT) {
            ta = *(const float4*)(Ar + (kt + 1) * 16 + la_q);
            tb = *(const float4*)(Wr + (kt + 1) * 16 + la_q);
        }
        #pragma unroll
        for (int kk = 0; kk < 16; kk++) {
            float4 a = *(const float4*)&As[cur][kk][tr * 4];
            float4 b = *(const float4*)&Bs[cur][kk][tc * 4];
            float ra[4] = {a.x, a.y, a.z, a.w};
            float rb[4] = {b.x, b.y, b.z, b.w};
            #pragma unroll
            for (int i = 0; i < 4; i++)
                #pragma unroll
                for (int j = 0; j < 4; j++)
                    acc[i][j] += ra[i] * rb[j];
        }
        if (kt + 1 < KT) {
            int nb = cur ^ 1;
            As[nb][la_q + 0][la_row] = ta.x; As[nb][la_q + 1][la_row] = ta.y;
            As[nb][la_q + 2][la_row] = ta.z; As[nb][la_q + 3][la_row] = ta.w;
            Bs[nb][la_q + 0][la_row] = tb.x; Bs[nb][la_q + 1][la_row] = tb.y;
            Bs[nb][la_q + 2][la_row] = tb.z; Bs[nb][la_q + 3][la_row] = tb.w;
            __syncthreads();
            cur ^= 1;
        }
    }

    const int col = nBase + tc * 4;
    float4 bb = *(const float4*)(bias + col);
    float rb4[4] = {bb.x, bb.y, bb.z, bb.w};
    #pragma unroll
    for (int i = 0; i < 4; i++) {
        int m = mBase + tr * 4 + i;
        float4 v;
        v.x = alpha * (acc[i][0] + biasScale * rb4[0]);
        v.y = alpha * (acc[i][1] + biasScale * rb4[1]);
        v.z = alpha * (acc[i][2] + biasScale * rb4[2]);
        v.w = alpha * (acc[i][3] + biasScale * rb4[3]);
        *(float4*)(out + (long)m * N + col) = v;
    }
}

// ---------------------------------------------------------------------------
// fp16 tensor-core GEMM (mma.sync.m16n8k16 + ldmatrix), cp.async 3-stage ring.
// CTA tile 128(M) x 256(N), 8 warps (2x4), warp tile 64x64. BK=32. fp32 accum.
// A: MxK fp16 row-major; W: NxK fp16 row-major (computes A @ W^T).
// EPI=0: out(float) = acc + bias[n]
// EPI=1: out(half)  = fp16((acc + bias[n]) * s[(r*B+n_b)*H + col/64])
// Row stride 40 halves (20 words): ldmatrix row addrs land on distinct banks.
// ---------------------------------------------------------------------------
#define HBK 32                    // K per stage (halves)
#define HLDW 20                   // row stride in 32-bit words (40 halves)
#define ASTG (128 * HLDW)         // A stage words (2560)
#define BSTG (256 * HLDW)         // B stage words (5120)
#define HNST 3
#define HSMEM_BYTES (HNST * (ASTG + BSTG) * 4)   // 92160

__device__ __forceinline__ void cp16(void* dst, const void* src) {
    uint32_t d = smem_u32(dst);
    asm volatile("cp.async.cg.shared.global [%0], [%1], 16;\n" :: "r"(d), "l"(src));
}

__device__ __forceinline__ void ldsm4(uint32_t* r, uint32_t addr) {
    asm volatile("ldmatrix.sync.aligned.m8n8.x4.shared.b16 {%0,%1,%2,%3}, [%4];"
                 : "=r"(r[0]), "=r"(r[1]), "=r"(r[2]), "=r"(r[3]) : "r"(addr));
}

__device__ __forceinline__ void mma16(float* d, const uint32_t* a, const uint32_t* b) {
    asm volatile(
        "mma.sync.aligned.m16n8k16.row.col.f32.f16.f16.f32 "
        "{%0,%1,%2,%3}, {%4,%5,%6,%7}, {%8,%9}, {%0,%1,%2,%3};"
        : "+f"(d[0]), "+f"(d[1]), "+f"(d[2]), "+f"(d[3])
        : "r"(a[0]), "r"(a[1]), "r"(a[2]), "r"(a[3]), "r"(b[0]), "r"(b[1]));
}

template<int EPI, typename OutT>
__global__ __launch_bounds__(256)
void hmma_gemm(const __half* __restrict__ A, const __half* __restrict__ W,
               const float* __restrict__ bias, OutT* __restrict__ out,
               int M, int N, int K, const float* __restrict__ sArr)
{
    extern __shared__ uint32_t smw[];
    uint32_t* AsBase = smw;                       // HNST * ASTG
    uint32_t* BsBase = smw + HNST * ASTG;         // HNST * BSTG

    const int tid  = threadIdx.x;
    const int w    = tid >> 5;
    const int lane = tid & 31;
    const int wm   = w >> 2;        // 0..1  -> m offset 64*wm
    const int wn   = w & 3;         // 0..3  -> n offset 64*wn
    const int lr   = lane >> 2;     // 0..7
    const int lc   = lane & 3;      // 0..3

    const __half* Ag = A + (size_t)(blockIdx.y * 128) * K;
    const __half* Wg = W + (size_t)(blockIdx.x * 256) * K;

    float acc[4][8][4];
    #pragma unroll
    for (int i = 0; i < 4; i++)
        #pragma unroll
        for (int j = 0; j < 8; j++)
            #pragma unroll
            for (int t = 0; t < 4; t++) acc[i][j][t] = 0.f;

    const int KT = K / HBK;   // 24

    // ldmatrix per-lane address components (within a stage)
    const int lq  = lane >> 3;          // quadrant 0..3
    const int l7  = lane & 7;
    // A tile i: row = wm*64 + i*16 + (lq&1)*8 + l7 ; colw = kc*8 + (lq>>1)*4
    const int aRowB = wm * 64 + (lq & 1) * 8 + l7;
    const int aColW = (lq >> 1) * 4;
    // B pair jj: row = wn*64 + (2jj + (lq>>1))*8 + l7 ; colw = kc*8 + (lq&1)*4
    const int bRowB = wn * 64 + (lq >> 1) * 8 + l7;
    const int bColW = (lq & 1) * 4;

    // prologue: stages 0..HNST-2
    #pragma unroll
    for (int s = 0; s < HNST - 1; s++) {
        #pragma unroll
        for (int l = 0; l < 2; l++) {           // A: 512 chunks
            int f = l * 256 + tid;
            int row = f >> 2, q = f & 3;
            cp16(&AsBase[s * ASTG + row * HLDW + q * 4],
                 Ag + (size_t)row * K + s * HBK + q * 8);
        }
        #pragma unroll
        for (int l = 0; l < 4; l++) {           // B: 1024 chunks
            int f = l * 256 + tid;
            int row = f >> 2, q = f & 3;
            cp16(&BsBase[s * BSTG + row * HLDW + q * 4],
                 Wg + (size_t)row * K + s * HBK + q * 8);
        }
        asm volatile("cp.async.commit_group;\n");
    }

    int sc = 0, sl = HNST - 1;
    for (int kt = 0; kt < KT; kt++) {
        asm volatile("cp.async.wait_group %0;\n" :: "n"(HNST - 2) : "memory");
        __syncthreads();

        const uint32_t aByte = smem_u32(AsBase + sc * ASTG);
        const uint32_t bByte = smem_u32(BsBase + sc * BSTG);
        #pragma unroll
        for (int kc = 0; kc < 2; kc++) {
            uint32_t af[4][4], bf[8][2];
            #pragma unroll
            for (int i = 0; i < 4; i++)
                ldsm4(af[i], aByte + ((aRowB + i * 16) * HLDW + kc * 8 + aColW) * 4);
            #pragma unroll
            for (int jj = 0; jj < 4; jj++) {
                uint32_t r[4];
                ldsm4(r, bByte + ((bRowB + jj * 16) * HLDW + kc * 8 + bColW) * 4);
                bf[2 * jj][0] = r[0]; bf[2 * jj][1] = r[1];
                bf[2 * jj + 1][0] = r[2]; bf[2 * jj + 1][1] = r[3];
            }
            #pragma unroll
            for (int i = 0; i < 4; i++)
                #pragma unroll
                for (int j = 0; j < 8; j++)
                    mma16(acc[i][j], af[i], bf[j]);
        }

        const int ktNext = kt + HNST - 1;
        if (ktNext < KT) {
            #pragma unroll
            for (int l = 0; l < 2; l++) {
                int f = l * 256 + tid;
                int row = f >> 2, q = f & 3;
                cp16(&AsBase[sl * ASTG + row * HLDW + q * 4],
                     Ag + (size_t)row * K + ktNext * HBK + q * 8);
            }
            #pragma unroll
            for (int l = 0; l < 4; l++) {
                int f = l * 256 + tid;
                int row = f >> 2, q = f & 3;
                cp16(&BsBase[sl * BSTG + row * HLDW + q * 4],
                     Wg + (size_t)row * K + ktNext * HBK + q * 8);
            }
        }
        asm volatile("cp.async.commit_group;\n");

        sc = (sc + 1 == HNST) ? 0 : sc + 1;
        sl = (sl + 1 == HNST) ? 0 : sl + 1;
    }

    // epilogue (acc rows lr, lr+8; cols 2lc, 2lc+1)
    const int mW = blockIdx.y * 128 + wm * 64;
    const int nW = blockIdx.x * 256 + wn * 64;
    const int headW = nW >> 6;   // warp's 64 cols are one head (64-aligned)
    #pragma unroll
    for (int i = 0; i < 4; i++) {
        int row0 = mW + i * 16 + lr;
        int row1 = row0 + 8;
        float s0 = 1.f, s1 = 1.f;
        if (EPI == 1) {
            s0 = sArr[((row0 >> 10) * B_DIM + (row0 & 3)) * H_DIM + headW];
            s1 = sArr[((row1 >> 10) * B_DIM + (row1 & 3)) * H_DIM + headW];
        }
        #pragma unroll
        for (int j = 0; j < 8; j++) {
            int col = nW + j * 8 + lc * 2;
            float b0 = bias[col], b1 = bias[col + 1];
            if (EPI == 0) {
                float v00 = acc[i][j][0] + b0, v01 = acc[i][j][1] + b1;
                float v10 = acc[i][j][2] + b0, v11 = acc[i][j][3] + b1;
                *(float2*)((float*)out + (size_t)row0 * N + col) = make_float2(v00, v01);
                *(float2*)((float*)out + (size_t)row1 * N + col) = make_float2(v10, v11);
            } else {
                __half2 h0 = __floats2half2_rn((acc[i][j][0] + b0) * s0,
                                               (acc[i][j][1] + b1) * s0);
                __half2 h1 = __floats2half2_rn((acc[i][j][2] + b0) * s1,
                                               (acc[i][j][3] + b1) * s1);
                *(__half2*)((__half*)out + (size_t)row0 * N + col) = h0;
                *(__half2*)((__half*)out + (size_t)row1 * N + col) = h1;
            }
        }
    }
}

// ---------------------------------------------------------------------------
// Attention: scores + softmax over r + sum over q -> s[(r*B+n)*H + h]
// ---------------------------------------------------------------------------
__global__ void attn_kernel(const float* __restrict__ qp,
                            const float* __restrict__ ksum,
                            float* __restrict__ sOut)
{
    const int h = blockIdx.x / B_DIM;
    const int n = blockIdx.x % B_DIM;
    const int qBase = blockIdx.y * 64;
    const int tid = threadIdx.x;

    __shared__ float ks[R_DIM][D_DIM + 1];
    __shared__ float qs[64][D_DIM + 1];

    for (int l = tid; l < 64 * 64; l += 256) {
        int r = l >> 6, d = l & 63;
        ks[r][d] = ksum[(r * B_DIM + n) * E_DIM + h * D_DIM + d];
        qs[r][d] = qp[((qBase + r) * B_DIM + n) * E_DIM + h * D_DIM + d];
    }
    __syncthreads();

    const int w = tid >> 5, lane = tid & 31;
    float acc0 = 0.f, acc1 = 0.f;
    #pragma unroll 1
    for (int qq = 0; qq < 8; qq++) {
        int q = w * 8 + qq;
        float d0 = 0.f, d1 = 0.f;
        #pragma unroll
        for (int d = 0; d < D_DIM; d++) {
            float qv = qs[q][d];
            d0 += qv * ks[lane][d];
            d1 += qv * ks[lane + 32][d];
        }
        float mx = fmaxf(d0, d1);
        #pragma unroll
        for (int o = 16; o; o >>= 1) mx = fmaxf(mx, __shfl_xor_sync(0xffffffffu, mx, o));
        float e0 = expf(d0 - mx), e1 = expf(d1 - mx);
        float sm = e0 + e1;
        #pragma unroll
        for (int o = 16; o; o >>= 1) sm += __shfl_xor_sync(0xffffffffu, sm, o);
        float inv = 1.f / sm;
        acc0 += e0 * inv;
        acc1 += e1 * inv;
    }
    atomicAdd(&sOut[(lane * B_DIM + n) * H_DIM + h], acc0);
    atomicAdd(&sOut[((lane + 32) * B_DIM + n) * H_DIM + h], acc1);
}

// ---------------------------------------------------------------------------
// Launch
// ---------------------------------------------------------------------------
extern "C" void kernel_launch(void* const* d_in, const int* in_sizes, int n_in,
                              void* d_out, int out_size)
{
    const float* x     = (const float*)d_in[0];
    const float* query = (const float*)d_in[1];
    const float* Wq    = (const float*)d_in[2];
    const float* bq    = (const float*)d_in[3];
    const float* Wk    = (const float*)d_in[4];
    const float* bk    = (const float*)d_in[5];
    const float* Wv    = (const float*)d_in[6];
    const float* bv    = (const float*)d_in[7];
    const float* Wo    = (const float*)d_in[8];
    const float* bo    = (const float*)d_in[9];
    float* out = (float*)d_out;

    void *p_xsum, *p_qp, *p_ksum, *p_s, *p_ctx, *p_x16, *p_hWv, *p_hWo;
    cudaGetSymbolAddress(&p_xsum, g_xsum);
    cudaGetSymbolAddress(&p_qp,   g_qp);
    cudaGetSymbolAddress(&p_ksum, g_ksum);
    cudaGetSymbolAddress(&p_s,    g_s);
    cudaGetSymbolAddress(&p_ctx,  g_ctx16);
    cudaGetSymbolAddress(&p_x16,  g_x16);
    cudaGetSymbolAddress(&p_hWv,  g_hWv);
    cudaGetSymbolAddress(&p_hWo,  g_hWo);
    float*  xsum = (float*)p_xsum;
    float*  qp   = (float*)p_qp;
    float*  ksum = (float*)p_ksum;
    float*  sArr = (float*)p_s;
    __half* ctx  = (__half*)p_ctx;
    __half* x16  = (__half*)p_x16;
    __half* hWv  = (__half*)p_hWv;
    __half* hWo  = (__half*)p_hWo;

    cudaFuncSetAttribute(hmma_gemm<0, float>,
                         cudaFuncAttributeMaxDynamicSharedMemorySize, HSMEM_BYTES);
    cudaFuncSetAttribute(hmma_gemm<1, __half>,
                         cudaFuncAttributeMaxDynamicSharedMemorySize, HSMEM_BYTES);

    const float scaling = (1.0f / 8.0f) / 16.0f;   // D^-0.5 / sqrt(Q)

    cudaMemsetAsync(sArr, 0, R_DIM * B_DIM * H_DIM * sizeof(float));

    // 1) column-sum of x + fp16 conversion
    xsum_kernel<<<(R_DIM * B_DIM * E_DIM) / 256, 256>>>(x, xsum, x16);

    // 1b) convert weights to fp16
    convw_kernel<<<(E_DIM * E_DIM) / 256, 256>>>(Wv, Wo, hWv, hWo);

    // 2) q projection (scaled), fp32
    sgemm64<<<dim3(E_DIM / 64, (Q_DIM * B_DIM) / 64), 256>>>(
        query, Wq, bq, qp, Q_DIM * B_DIM, E_DIM, QD_DIM, scaling, 1.0f);

    // 3) ksum = xsum @ Wk^T + C*bk, fp32
    sgemm64<<<dim3(E_DIM / 64, (R_DIM * B_DIM) / 64), 256>>>(
        xsum, Wk, bk, ksum, R_DIM * B_DIM, E_DIM, E_DIM, 1.0f, (float)C_DIM);

    // 4) scores + softmax + sum over q -> s
    attn_kernel<<<dim3(H_DIM * B_DIM, Q_DIM / 64), 256>>>(qp, ksum, sArr);

    // 5) ctx = fp16( s .* (x16 @ hWv^T + bv) )   [fp16 tensor cores, ldmatrix]
    hmma_gemm<1, __half><<<dim3(E_DIM / 256, M_BIG / 128), 256, HSMEM_BYTES>>>(
        x16, hWv, bv, ctx, M_BIG, E_DIM, E_DIM, sArr);

    // 6) out = ctx @ hWo^T + bo                  [fp16 tensor cores, ldmatrix]
    hmma_gemm<0, float><<<dim3(E_DIM / 256, M_BIG / 128), 256, HSMEM_BYTES>>>(
        ctx, hWo, bo, out, M_BIG, E_DIM, E_DIM, nullptr);
}

// round 13
// speedup vs baseline: 6.2020x; 1.1281x over previous
#include <cuda_runtime.h>
#include <cuda_fp16.h>
#include <cstdint>

// Problem constants
#define R_DIM 64
#define C_DIM 256
#define B_DIM 4
#define E_DIM 768
#define Q_DIM 256
#define QD_DIM 512
#define H_DIM 12
#define D_DIM 64
#define M_BIG (R_DIM * C_DIM * B_DIM)   // 65536
#define EK (E_DIM * E_DIM)              // 589824
#define RN_CNT (R_DIM * B_DIM)          // 256

// Scratch (device globals; no allocation in kernel_launch)
__device__ __align__(16) float  g_xsum[RN_CNT * E_DIM];
__device__ __align__(16) float  g_qp[Q_DIM * B_DIM * E_DIM];
__device__ __align__(16) float  g_ksum[RN_CNT * E_DIM];
__device__ __align__(16) float  g_s[RN_CNT * H_DIM];
__device__ __align__(16) __half g_x16p[M_BIG * E_DIM];   // fp16 x, [rn*256+c, e] layout
__device__ __align__(16) __half g_hWo[EK];
__device__ __align__(16) __half g_hWvT[EK];              // Wv transposed
__device__ __align__(16) float  g_K32[H_DIM * EK];       // K_h fp32, [h][e*768+k]
__device__ __align__(16) __half g_KT[EK * 32];           // [ek][h] padded to 32
__device__ __align__(16) __half g_s16[RN_CNT * 32];      // s fp16, h padded to 32
__device__ __align__(16) float  g_pb[H_DIM * E_DIM];
__device__ __align__(16) float  g_q[RN_CNT * E_DIM];     // per-group output bias
__device__ __align__(16) __half g_M[(size_t)RN_CNT * EK]; // 302 MB combined matrices

__device__ __forceinline__ uint32_t smem_u32(const void* p) {
    return (uint32_t)__cvta_generic_to_shared(p);
}

// ---------------------------------------------------------------------------
// xsum[rn,e] = sum_c x[r,c,n,e]; also x16p[(rn*256+c)*768+e] = fp16(x)
// ---------------------------------------------------------------------------
__global__ void xsum_kernel(const float* __restrict__ x,
                            float* __restrict__ xsum,
                            __half* __restrict__ x16p)
{
    int o = blockIdx.x * 256 + threadIdx.x;
    int e = o % E_DIM;
    int rn = o / E_DIM;
    int r = rn / B_DIM;
    int n = rn % B_DIM;
    const long base = ((long)(r * C_DIM) * B_DIM + n) * E_DIM + e;
    const long stride = (long)B_DIM * E_DIM;
    const size_t pbase = ((size_t)rn * C_DIM) * E_DIM + e;
    float a0 = 0.f, a1 = 0.f, a2 = 0.f, a3 = 0.f;
    #pragma unroll 4
    for (int c = 0; c < C_DIM; c += 4) {
        float v0 = x[base + (long)(c + 0) * stride];
        float v1 = x[base + (long)(c + 1) * stride];
        float v2 = x[base + (long)(c + 2) * stride];
        float v3 = x[base + (long)(c + 3) * stride];
        a0 += v0; a1 += v1; a2 += v2; a3 += v3;
        x16p[pbase + (size_t)(c + 0) * E_DIM] = __float2half_rn(v0);
        x16p[pbase + (size_t)(c + 1) * E_DIM] = __float2half_rn(v1);
        x16p[pbase + (size_t)(c + 2) * E_DIM] = __float2half_rn(v2);
        x16p[pbase + (size_t)(c + 3) * E_DIM] = __float2half_rn(v3);
    }
    xsum[o] = (a0 + a1) + (a2 + a3);
}

// ---------------------------------------------------------------------------
// Convert Wo->fp16 linear; Wv->fp16 transposed (hWvT[a*768+b] = Wv[b*768+a])
// grid (24,24), block (32,8)
// ---------------------------------------------------------------------------
__global__ void convw_kernel(const float* __restrict__ Wv, const float* __restrict__ Wo,
                             __half* __restrict__ hWvT, __half* __restrict__ hWo)
{
    __shared__ float t[32][33];
    const int bx = blockIdx.x * 32, by = blockIdx.y * 32;
    const int tx = threadIdx.x, ty = threadIdx.y;
    #pragma unroll
    for (int i = 0; i < 32; i += 8)
        t[ty + i][tx] = Wv[(size_t)(by + ty + i) * E_DIM + bx + tx];
    __syncthreads();
    #pragma unroll
    for (int i = 0; i < 32; i += 8)
        hWvT[(size_t)(bx + ty + i) * E_DIM + by + tx] = __float2half_rn(t[tx][ty + i]);
    // linear Wo conversion: 576 blocks x 1024 elements
    int base = (blockIdx.y * 24 + blockIdx.x) * 1024 + (ty * 32 + tx) * 4;
    #pragma unroll
    for (int j = 0; j < 4; j++)
        hWo[base + j] = __float2half_rn(Wo[base + j]);
}

// ---------------------------------------------------------------------------
// fp32 SIMT SGEMM, 64x64 tiles (small accuracy-critical projections)
// ---------------------------------------------------------------------------
__global__ __launch_bounds__(256)
void sgemm64(const float* __restrict__ A, const float* __restrict__ W,
             const float* __restrict__ bias, float* __restrict__ out,
             int M, int N, int K, float alpha, float biasScale)
{
    __shared__ __align__(16) float As[2][16][68];
    __shared__ __align__(16) float Bs[2][16][68];

    const int tid = threadIdx.x;
    const int mBase = blockIdx.y * 64;
    const int nBase = blockIdx.x * 64;
    const int tr = tid >> 4;
    const int tc = tid & 15;
    const int la_row = tid >> 2;
    const int la_q   = (tid & 3) * 4;

    const float* Ar = A + (long)(mBase + la_row) * K;
    const float* Wr = W + (long)(nBase + la_row) * K;

    float acc[4][4];
    #pragma unroll
    for (int i = 0; i < 4; i++)
        #pragma unroll
        for (int j = 0; j < 4; j++) acc[i][j] = 0.f;

    float4 ta, tb;
    ta = *(const float4*)(Ar + la_q);
    tb = *(const float4*)(Wr + la_q);
    As[0][la_q + 0][la_row] = ta.x; As[0][la_q + 1][la_row] = ta.y;
    As[0][la_q + 2][la_row] = ta.z; As[0][la_q + 3][la_row] = ta.w;
    Bs[0][la_q + 0][la_row] = tb.x; Bs[0][la_q + 1][la_row] = tb.y;
    Bs[0][la_q + 2][la_row] = tb.z; Bs[0][la_q + 3][la_row] = tb.w;
    __syncthreads();

    const int KT = K / 16;
    int cur = 0;
    for (int kt = 0; kt < KT; kt++) {
        if (kt + 1 < KT) {
            ta = *(const float4*)(Ar + (kt + 1) * 16 + la_q);
            tb = *(const float4*)(Wr + (kt + 1) * 16 + la_q);
        }
        #pragma unroll
        for (int kk = 0; kk < 16; kk++) {
            float4 a = *(const float4*)&As[cur][kk][tr * 4];
            float4 b = *(const float4*)&Bs[cur][kk][tc * 4];
            float ra[4] = {a.x, a.y, a.z, a.w};
            float rb[4] = {b.x, b.y, b.z, b.w};
            #pragma unroll
            for (int i = 0; i < 4; i++)
                #pragma unroll
                for (int j = 0; j < 4; j++)
                    acc[i][j] += ra[i] * rb[j];
        }
        if (kt + 1 < KT) {
            int nb = cur ^ 1;
            As[nb][la_q + 0][la_row] = ta.x; As[nb][la_q + 1][la_row] = ta.y;
            As[nb][la_q + 2][la_row] = ta.z; As[nb][la_q + 3][la_row] = ta.w;
            Bs[nb][la_q + 0][la_row] = tb.x; Bs[nb][la_q + 1][la_row] = tb.y;
            Bs[nb][la_q + 2][la_row] = tb.z; Bs[nb][la_q + 3][la_row] = tb.w;
            __syncthreads();
            cur ^= 1;
        }
    }

    const int col = nBase + tc * 4;
    float4 bb = *(const float4*)(bias + col);
    float rb4[4] = {bb.x, bb.y, bb.z, bb.w};
    #pragma unroll
    for (int i = 0; i < 4; i++) {
        int m = mBase + tr * 4 + i;
        float4 v;
        v.x = alpha * (acc[i][0] + biasScale * rb4[0]);
        v.y = alpha * (acc[i][1] + biasScale * rb4[1]);
        v.z = alpha * (acc[i][2] + biasScale * rb4[2]);
        v.w = alpha * (acc[i][3] + biasScale * rb4[3]);
        *(float4*)(out + (long)m * N + col) = v;
    }
}

// ---------------------------------------------------------------------------
// Generic fp16 tensor-core GEMM (mma.sync.m16n8k16 + ldmatrix), 3-stage cp.async.
// CTA tile 128(M) x 256(N), 8 warps (2x4), warp tile 64x64, fp32 accum.
// out[m,n] = epi( sum_k A[m + 128*by, k] * W[n + 256*bx, k] ) with z offsets.
// EPI=2: out(half)  = fp16(acc), plain rows
// EPI=3: out(float) = acc + bias[(by>>1)*biasM + n], rows permuted rn-group -> orig
// EPI=4: out(float) = acc, plain rows
// ---------------------------------------------------------------------------
#define HBK 32                    // K per stage (halves)
#define HLDW 20                   // row stride in 32-bit words (40 halves)
#define ASTG (128 * HLDW)
#define BSTG (256 * HLDW)
#define HNST 3
#define HSMEM_BYTES (HNST * (ASTG + BSTG) * 4)   // 92160

__device__ __forceinline__ void cp16(void* dst, const void* src) {
    uint32_t d = smem_u32(dst);
    asm volatile("cp.async.cg.shared.global [%0], [%1], 16;\n" :: "r"(d), "l"(src));
}

__device__ __forceinline__ void ldsm4(uint32_t* r, uint32_t addr) {
    asm volatile("ldmatrix.sync.aligned.m8n8.x4.shared.b16 {%0,%1,%2,%3}, [%4];"
                 : "=r"(r[0]), "=r"(r[1]), "=r"(r[2]), "=r"(r[3]) : "r"(addr));
}

__device__ __forceinline__ void mma16(float* d, const uint32_t* a, const uint32_t* b) {
    asm volatile(
        "mma.sync.aligned.m16n8k16.row.col.f32.f16.f16.f32 "
        "{%0,%1,%2,%3}, {%4,%5,%6,%7}, {%8,%9}, {%0,%1,%2,%3};"
        : "+f"(d[0]), "+f"(d[1]), "+f"(d[2]), "+f"(d[3])
        : "r"(a[0]), "r"(a[1]), "r"(a[2]), "r"(a[3]), "r"(b[0]), "r"(b[1]));
}

template<int EPI, typename OutT>
__global__ __launch_bounds__(256)
void hmma_gemm(const __half* __restrict__ A, int lda, size_t aZ,
               const __half* __restrict__ W, int ldb, size_t bZ, size_t bM,
               const float* __restrict__ bias, int biasM,
               OutT* __restrict__ out, int ldo, size_t oZ,
               int K)
{
    extern __shared__ uint32_t smw[];
    uint32_t* AsBase = smw;
    uint32_t* BsBase = smw + HNST * ASTG;

    const int tid  = threadIdx.x;
    const int w    = tid >> 5;
    const int lane = tid & 31;
    const int wm   = w >> 2;
    const int wn   = w & 3;
    const int lr   = lane >> 2;
    const int lc   = lane & 3;

    const __half* Ag = A + (size_t)blockIdx.y * 128 * lda + (size_t)blockIdx.z * aZ;
    const __half* Wg = W + (size_t)blockIdx.x * 256 * ldb + (size_t)blockIdx.z * bZ
                         + (size_t)(blockIdx.y >> 1) * bM;

    float acc[4][8][4];
    #pragma unroll
    for (int i = 0; i < 4; i++)
        #pragma unroll
        for (int j = 0; j < 8; j++)
            #pragma unroll
            for (int t = 0; t < 4; t++) acc[i][j][t] = 0.f;

    const int KT = K / HBK;

    const int lq = lane >> 3;
    const int l7 = lane & 7;
    const int aRowB = wm * 64 + (lq & 1) * 8 + l7;
    const int aColW = (lq >> 1) * 4;
    const int bRowB = wn * 64 + (lq >> 1) * 8 + l7;
    const int bColW = (lq & 1) * 4;

    // prologue (guarded for short K)
    #pragma unroll
    for (int s = 0; s < HNST - 1; s++) {
        if (s < KT) {
            #pragma unroll
            for (int l = 0; l < 2; l++) {
                int f = l * 256 + tid;
                int row = f >> 2, q = f & 3;
                cp16(&AsBase[s * ASTG + row * HLDW + q * 4],
                     Ag + (size_t)row * lda + s * HBK + q * 8);
            }
            #pragma unroll
            for (int l = 0; l < 4; l++) {
                int f = l * 256 + tid;
                int row = f >> 2, q = f & 3;
                cp16(&BsBase[s * BSTG + row * HLDW + q * 4],
                     Wg + (size_t)row * ldb + s * HBK + q * 8);
            }
        }
        asm volatile("cp.async.commit_group;\n");
    }

    int sc = 0, sl = HNST - 1;
    for (int kt = 0; kt < KT; kt++) {
        asm volatile("cp.async.wait_group %0;\n" :: "n"(HNST - 2) : "memory");
        __syncthreads();

        const uint32_t aByte = smem_u32(AsBase + sc * ASTG);
        const uint32_t bByte = smem_u32(BsBase + sc * BSTG);
        #pragma unroll
        for (int kc = 0; kc < 2; kc++) {
            uint32_t af[4][4], bf[8][2];
            #pragma unroll
            for (int i = 0; i < 4; i++)
                ldsm4(af[i], aByte + ((aRowB + i * 16) * HLDW + kc * 8 + aColW) * 4);
            #pragma unroll
            for (int jj = 0; jj < 4; jj++) {
                uint32_t r[4];
                ldsm4(r, bByte + ((bRowB + jj * 16) * HLDW + kc * 8 + bColW) * 4);
                bf[2 * jj][0] = r[0]; bf[2 * jj][1] = r[1];
                bf[2 * jj + 1][0] = r[2]; bf[2 * jj + 1][1] = r[3];
            }
            #pragma unroll
            for (int i = 0; i < 4; i++)
                #pragma unroll
                for (int j = 0; j < 8; j++)
                    mma16(acc[i][j], af[i], bf[j]);
        }

        const int ktNext = kt + HNST - 1;
        if (ktNext < KT) {
            #pragma unroll
            for (int l = 0; l < 2; l++) {
                int f = l * 256 + tid;
                int row = f >> 2, q = f & 3;
                cp16(&AsBase[sl * ASTG + row * HLDW + q * 4],
                     Ag + (size_t)row * lda + ktNext * HBK + q * 8);
            }
            #pragma unroll
            for (int l = 0; l < 4; l++) {
                int f = l * 256 + tid;
                int row = f >> 2, q = f & 3;
                cp16(&BsBase[sl * BSTG + row * HLDW + q * 4],
                     Wg + (size_t)row * ldb + ktNext * HBK + q * 8);
            }
        }
        asm volatile("cp.async.commit_group;\n");

        sc = (sc + 1 == HNST) ? 0 : sc + 1;
        sl = (sl + 1 == HNST) ? 0 : sl + 1;
    }

    // epilogue
    const int mW = blockIdx.y * 128 + wm * 64;
    const int nW = blockIdx.x * 256 + wn * 64;
    const float* biasp = (EPI == 3) ? bias + (size_t)(blockIdx.y >> 1) * biasM : bias;
    OutT* outp = out + (size_t)blockIdx.z * oZ;

    #pragma unroll
    for (int i = 0; i < 4; i++) {
        int row0 = mW + i * 16 + lr;
        int row1 = row0 + 8;
        size_t or0, or1;
        if (EPI == 3) {
            int rn = row0 >> 8;                 // same for row1 (64-row warp tile)
            int rbase = (rn >> 2) * 256, nb = rn & 3;
            or0 = ((size_t)(rbase + (row0 & 255))) * 4 + nb;
            or1 = ((size_t)(rbase + (row1 & 255))) * 4 + nb;
        } else {
            or0 = (size_t)row0; or1 = (size_t)row1;
        }
        #pragma unroll
        for (int j = 0; j < 8; j++) {
            int col = nW + j * 8 + lc * 2;
            if (EPI == 2) {
                __half2 h0 = __floats2half2_rn(acc[i][j][0], acc[i][j][1]);
                __half2 h1 = __floats2half2_rn(acc[i][j][2], acc[i][j][3]);
                *(__half2*)((__half*)outp + or0 * ldo + col) = h0;
                *(__half2*)((__half*)outp + or1 * ldo + col) = h1;
            } else if (EPI == 4) {
                *(float2*)((float*)outp + or0 * ldo + col) =
                    make_float2(acc[i][j][0], acc[i][j][1]);
                *(float2*)((float*)outp + or1 * ldo + col) =
                    make_float2(acc[i][j][2], acc[i][j][3]);
            } else {   // EPI == 3
                float b0 = biasp[col], b1 = biasp[col + 1];
                *(float2*)((float*)outp + or0 * ldo + col) =
                    make_float2(acc[i][j][0] + b0, acc[i][j][1] + b1);
                *(float2*)((float*)outp + or1 * ldo + col) =
                    make_float2(acc[i][j][2] + b0, acc[i][j][3] + b1);
            }
        }
    }
}

// ---------------------------------------------------------------------------
// Attention: scores + softmax over r + sum over q -> s[rn*H + h]
// ---------------------------------------------------------------------------
__global__ void attn_kernel(const float* __restrict__ qp,
                            const float* __restrict__ ksum,
                            float* __restrict__ sOut)
{
    const int h = blockIdx.x / B_DIM;
    const int n = blockIdx.x % B_DIM;
    const int qBase = blockIdx.y * 64;
    const int tid = threadIdx.x;

    __shared__ float ks[R_DIM][D_DIM + 1];
    __shared__ float qs[64][D_DIM + 1];

    for (int l = tid; l < 64 * 64; l += 256) {
        int r = l >> 6, d = l & 63;
        ks[r][d] = ksum[(r * B_DIM + n) * E_DIM + h * D_DIM + d];
        qs[r][d] = qp[((qBase + r) * B_DIM + n) * E_DIM + h * D_DIM + d];
    }
    __syncthreads();

    const int w = tid >> 5, lane = tid & 31;
    float acc0 = 0.f, acc1 = 0.f;
    #pragma unroll 1
    for (int qq = 0; qq < 8; qq++) {
        int q = w * 8 + qq;
        float d0 = 0.f, d1 = 0.f;
        #pragma unroll
        for (int d = 0; d < D_DIM; d++) {
            float qv = qs[q][d];
            d0 += qv * ks[lane][d];
            d1 += qv * ks[lane + 32][d];
        }
        float mx = fmaxf(d0, d1);
        #pragma unroll
        for (int o = 16; o; o >>= 1) mx = fmaxf(mx, __shfl_xor_sync(0xffffffffu, mx, o));
        float e0 = expf(d0 - mx), e1 = expf(d1 - mx);
        float sm = e0 + e1;
        #pragma unroll
        for (int o = 16; o; o >>= 1) sm += __shfl_xor_sync(0xffffffffu, sm, o);
        float inv = 1.f / sm;
        acc0 += e0 * inv;
        acc1 += e1 * inv;
    }
    atomicAdd(&sOut[(lane * B_DIM + n) * H_DIM + h], acc0);
    atomicAdd(&sOut[((lane + 32) * B_DIM + n) * H_DIM + h], acc1);
}

// ---------------------------------------------------------------------------
// Small prep kernels
// ---------------------------------------------------------------------------
// KT[ek*32 + h] = fp16(K32[h*EK + ek]), zero-padded to 32
__global__ void repack_kernel(const float* __restrict__ K32, __half* __restrict__ KT)
{
    int ek = blockIdx.x * 256 + threadIdx.x;
    __half v[32];
    #pragma unroll
    for (int h = 0; h < H_DIM; h++)
        v[h] = __float2half_rn(K32[(size_t)h * EK + ek]);
    #pragma unroll
    for (int h = H_DIM; h < 32; h++) v[h] = __ushort_as_half(0);
    uint4* d = (uint4*)(KT + (size_t)ek * 32);
    const uint4* s = (const uint4*)v;
    d[0] = s[0]; d[1] = s[1]; d[2] = s[2]; d[3] = s[3];
}

// s16[rn*32+h] = fp16(s[rn*12+h]) (padded)
__global__ void fill_s16_kernel(const float* __restrict__ s, __half* __restrict__ s16)
{
    int i = blockIdx.x * 256 + threadIdx.x;   // 8192 total
    int rn = i >> 5, h = i & 31;
    s16[i] = (h < H_DIM) ? __float2half_rn(s[rn * H_DIM + h]) : __ushort_as_half(0);
}

// pb[h*768+e] = sum_d bv[h*64+d] * Wo[e*768 + h*64+d]
__global__ void pb_kernel(const float* __restrict__ Wo, const float* __restrict__ bv,
                          float* __restrict__ pb)
{
    int h = blockIdx.x;
    int e = blockIdx.y * 128 + threadIdx.x;
    const float* wrow = Wo + (size_t)e * E_DIM + h * D_DIM;
    const float* b = bv + h * D_DIM;
    float a = 0.f;
    #pragma unroll
    for (int d = 0; d < D_DIM; d++) a += b[d] * wrow[d];
    pb[h * E_DIM + e] = a;
}

// q[rn*768+e] = bo[e] + sum_h s[rn*12+h] * pb[h*768+e]
__global__ void qbias_kernel(const float* __restrict__ s, const float* __restrict__ pb,
                             const float* __restrict__ bo, float* __restrict__ q)
{
    int rn = blockIdx.x;
    int e = blockIdx.y * 256 + threadIdx.x;
    float a = bo[e];
    #pragma unroll
    for (int h = 0; h < H_DIM; h++)
        a += s[rn * H_DIM + h] * pb[h * E_DIM + e];
    q[rn * E_DIM + e] = a;
}

// ---------------------------------------------------------------------------
// Launch
// ---------------------------------------------------------------------------
extern "C" void kernel_launch(void* const* d_in, const int* in_sizes, int n_in,
                              void* d_out, int out_size)
{
    const float* x     = (const float*)d_in[0];
    const float* query = (const float*)d_in[1];
    const float* Wq    = (const float*)d_in[2];
    const float* bq    = (const float*)d_in[3];
    const float* Wk    = (const float*)d_in[4];
    const float* bk    = (const float*)d_in[5];
    const float* Wv    = (const float*)d_in[6];
    const float* bv    = (const float*)d_in[7];
    const float* Wo    = (const float*)d_in[8];
    const float* bo    = (const float*)d_in[9];
    float* out = (float*)d_out;

    void *p;
    cudaGetSymbolAddress(&p, g_xsum);  float*  xsum = (float*)p;
    cudaGetSymbolAddress(&p, g_qp);    float*  qp   = (float*)p;
    cudaGetSymbolAddress(&p, g_ksum);  float*  ksum = (float*)p;
    cudaGetSymbolAddress(&p, g_s);     float*  sArr = (float*)p;
    cudaGetSymbolAddress(&p, g_x16p);  __half* x16p = (__half*)p;
    cudaGetSymbolAddress(&p, g_hWo);   __half* hWo  = (__half*)p;
    cudaGetSymbolAddress(&p, g_hWvT);  __half* hWvT = (__half*)p;
    cudaGetSymbolAddress(&p, g_K32);   float*  K32  = (float*)p;
    cudaGetSymbolAddress(&p, g_KT);    __half* KT   = (__half*)p;
    cudaGetSymbolAddress(&p, g_s16);   __half* s16  = (__half*)p;
    cudaGetSymbolAddress(&p, g_pb);    float*  pb   = (float*)p;
    cudaGetSymbolAddress(&p, g_q);     float*  q    = (float*)p;
    cudaGetSymbolAddress(&p, g_M);     __half* M    = (__half*)p;

    cudaFuncSetAttribute(hmma_gemm<2, __half>,
                         cudaFuncAttributeMaxDynamicSharedMemorySize, HSMEM_BYTES);
    cudaFuncSetAttribute(hmma_gemm<3, float>,
                         cudaFuncAttributeMaxDynamicSharedMemorySize, HSMEM_BYTES);
    cudaFuncSetAttribute(hmma_gemm<4, float>,
                         cudaFuncAttributeMaxDynamicSharedMemorySize, HSMEM_BYTES);

    const float scaling = (1.0f / 8.0f) / 16.0f;   // D^-0.5 / sqrt(Q)

    cudaMemsetAsync(sArr, 0, RN_CNT * H_DIM * sizeof(float));

    // 1) column-sum of x + fp16 permuted copy
    xsum_kernel<<<(RN_CNT * E_DIM) / 256, 256>>>(x, xsum, x16p);

    // 2) weight conversions (hWo linear, hWvT transposed)
    convw_kernel<<<dim3(24, 24), dim3(32, 8)>>>(Wv, Wo, hWvT, hWo);

    // 3) q projection (scaled), fp32
    sgemm64<<<dim3(E_DIM / 64, (Q_DIM * B_DIM) / 64), 256>>>(
        query, Wq, bq, qp, Q_DIM * B_DIM, E_DIM, QD_DIM, scaling, 1.0f);

    // 4) ksum = xsum @ Wk^T + C*bk, fp32
    sgemm64<<<dim3(E_DIM / 64, RN_CNT / 64), 256>>>(
        xsum, Wk, bk, ksum, RN_CNT, E_DIM, E_DIM, 1.0f, (float)C_DIM);

    // 5) attention -> s[rn,h]
    attn_kernel<<<dim3(H_DIM * B_DIM, Q_DIM / 64), 256>>>(qp, ksum, sArr);

    // 6) K_h[e,k] = Wo[:,hblk] @ Wv[hblk,:]  (fp16 in, fp32 out), z = head
    hmma_gemm<4, float><<<dim3(E_DIM / 256, E_DIM / 128, H_DIM), 256, HSMEM_BYTES>>>(
        hWo, E_DIM, (size_t)D_DIM,
        hWvT, E_DIM, (size_t)D_DIM, 0,
        nullptr, 0,
        K32, E_DIM, (size_t)EK,
        D_DIM);

    // 7) repack K -> KT[ek][h] fp16 (h padded to 32)
    repack_kernel<<<EK / 256, 256>>>(K32, KT);

    // 8) s -> fp16 padded
    fill_s16_kernel<<<(RN_CNT * 32) / 256, 256>>>(sArr, s16);

    // 9) bias precompute: pb, then q
    pb_kernel<<<dim3(H_DIM, E_DIM / 128), 128>>>(Wo, bv, pb);
    qbias_kernel<<<dim3(RN_CNT, E_DIM / 256), 256>>>(sArr, pb, bo, q);

    // 10) M[rn, ek] = sum_h s16[rn,h] * KT[ek,h]   (fp32 accum -> fp16)
    hmma_gemm<2, __half><<<dim3(EK / 256, RN_CNT / 128), 256, HSMEM_BYTES>>>(
        s16, 32, 0,
        KT, 32, 0, 0,
        nullptr, 0,
        M, EK, 0,
        32);

    // 11) out = x16p @ M_rn^T + q_rn  (rows permuted back to [r,c,n] layout)
    hmma_gemm<3, float><<<dim3(E_DIM / 256, M_BIG / 128), 256, HSMEM_BYTES>>>(
        x16p, E_DIM, 0,
        M, E_DIM, 0, (size_t)EK,
        q, E_DIM,
        out, E_DIM, 0,
        E_DIM);
}

// round 14
// speedup vs baseline: 6.4061x; 1.0329x over previous
#include <cuda_runtime.h>
#include <cuda_fp16.h>
#include <cstdint>

// Problem constants
#define R_DIM 64
#define C_DIM 256
#define B_DIM 4
#define E_DIM 768
#define Q_DIM 256
#define QD_DIM 512
#define H_DIM 12
#define D_DIM 64
#define M_BIG (R_DIM * C_DIM * B_DIM)   // 65536
#define EK (E_DIM * E_DIM)              // 589824
#define RN_CNT (R_DIM * B_DIM)          // 256

// Scratch (device globals; no allocation in kernel_launch)
__device__ __align__(16) float  g_xsum[RN_CNT * E_DIM];
__device__ __align__(16) float  g_qp[Q_DIM * B_DIM * E_DIM];
__device__ __align__(16) float  g_ksum[RN_CNT * E_DIM];
__device__ __align__(16) float  g_s[RN_CNT * H_DIM];
__device__ __align__(16) __half g_x16p[M_BIG * E_DIM];   // fp16 x, [rn*256+c, e]
__device__ __align__(16) __half g_hWo[EK];
__device__ __align__(16) __half g_hWvT[EK];              // Wv transposed
__device__ __align__(16) __half g_K16[H_DIM * EK];       // K_h fp16, [h][e*768+k]
__device__ __align__(16) __half g_KT[EK * 32];           // [ek][h] padded to 32
__device__ __align__(16) __half g_s16[RN_CNT * 32];      // s fp16, h padded to 32
__device__ __align__(16) float  g_pb[H_DIM * E_DIM];
__device__ __align__(16) float  g_q[RN_CNT * E_DIM];     // per-group output bias
__device__ __align__(16) __half g_M[(size_t)RN_CNT * EK]; // 302 MB combined matrices

__device__ __forceinline__ uint32_t smem_u32(const void* p) {
    return (uint32_t)__cvta_generic_to_shared(p);
}

// ---------------------------------------------------------------------------
// xsum[rn,e] = sum_c x[r,c,n,e]; also x16p[(rn*256+c)*768+e] = fp16(x)
// float4 over e: thread handles 4 consecutive e. grid 192 x 256 thr.
// ---------------------------------------------------------------------------
__global__ void xsum_kernel(const float* __restrict__ x,
                            float* __restrict__ xsum,
                            __half* __restrict__ x16p)
{
    int o = blockIdx.x * 256 + threadIdx.x;      // 0 .. RN_CNT*192-1
    int e4 = (o % 192) * 4;
    int rn = o / 192;
    int r = rn / B_DIM;
    int n = rn % B_DIM;
    const float* px = x + ((long)(r * C_DIM) * B_DIM + n) * E_DIM + e4;
    const long stride = (long)B_DIM * E_DIM;
    __half* pp = x16p + ((size_t)rn * C_DIM) * E_DIM + e4;

    float4 a = make_float4(0.f, 0.f, 0.f, 0.f);
    #pragma unroll 4
    for (int c = 0; c < C_DIM; c++) {
        float4 v = *(const float4*)(px + (long)c * stride);
        a.x += v.x; a.y += v.y; a.z += v.z; a.w += v.w;
        __half2* d = (__half2*)(pp + (size_t)c * E_DIM);
        d[0] = __floats2half2_rn(v.x, v.y);
        d[1] = __floats2half2_rn(v.z, v.w);
    }
    *(float4*)(xsum + rn * E_DIM + e4) = a;
}

// ---------------------------------------------------------------------------
// Convert Wo->fp16 linear; Wv->fp16 transposed
// ---------------------------------------------------------------------------
__global__ void convw_kernel(const float* __restrict__ Wv, const float* __restrict__ Wo,
                             __half* __restrict__ hWvT, __half* __restrict__ hWo)
{
    __shared__ float t[32][33];
    const int bx = blockIdx.x * 32, by = blockIdx.y * 32;
    const int tx = threadIdx.x, ty = threadIdx.y;
    #pragma unroll
    for (int i = 0; i < 32; i += 8)
        t[ty + i][tx] = Wv[(size_t)(by + ty + i) * E_DIM + bx + tx];
    __syncthreads();
    #pragma unroll
    for (int i = 0; i < 32; i += 8)
        hWvT[(size_t)(bx + ty + i) * E_DIM + by + tx] = __float2half_rn(t[tx][ty + i]);
    int base = (blockIdx.y * 24 + blockIdx.x) * 1024 + (ty * 32 + tx) * 4;
    #pragma unroll
    for (int j = 0; j < 4; j++)
        hWo[base + j] = __float2half_rn(Wo[base + j]);
}

// ---------------------------------------------------------------------------
// Merged fp32 projections: qp (192 blocks) + ksum (48 blocks), 64x64 tiles.
// isQ: A=query K=512 alpha=scaling biasScale=1 -> qp
// else A=xsum K=768 alpha=1 biasScale=256     -> ksum
// ---------------------------------------------------------------------------
__global__ __launch_bounds__(256)
void proj_kernel(const float* __restrict__ query, const float* __restrict__ Wq,
                 const float* __restrict__ bq, float* __restrict__ qp,
                 const float* __restrict__ xsum, const float* __restrict__ Wk,
                 const float* __restrict__ bk, float* __restrict__ ksum,
                 float scaling)
{
    const bool isQ = blockIdx.x < 192;
    const int bid = isQ ? blockIdx.x : blockIdx.x - 192;
    const int nBase = (bid % 12) * 64;
    const int mBase = (bid / 12) * 64;
    const float* A    = isQ ? query : xsum;
    const float* W    = isQ ? Wq : Wk;
    const float* bias = isQ ? bq : bk;
    float* out        = isQ ? qp : ksum;
    const int   K     = isQ ? QD_DIM : E_DIM;
    const float alpha = isQ ? scaling : 1.0f;
    const float bScal = isQ ? 1.0f : (float)C_DIM;

    __shared__ __align__(16) float As[2][16][68];
    __shared__ __align__(16) float Bs[2][16][68];

    const int tid = threadIdx.x;
    const int tr = tid >> 4;
    const int tc = tid & 15;
    const int la_row = tid >> 2;
    const int la_q   = (tid & 3) * 4;

    const float* Ar = A + (long)(mBase + la_row) * K;
    const float* Wr = W + (long)(nBase + la_row) * K;

    float acc[4][4];
    #pragma unroll
    for (int i = 0; i < 4; i++)
        #pragma unroll
        for (int j = 0; j < 4; j++) acc[i][j] = 0.f;

    float4 ta, tb;
    ta = *(const float4*)(Ar + la_q);
    tb = *(const float4*)(Wr + la_q);
    As[0][la_q + 0][la_row] = ta.x; As[0][la_q + 1][la_row] = ta.y;
    As[0][la_q + 2][la_row] = ta.z; As[0][la_q + 3][la_row] = ta.w;
    Bs[0][la_q + 0][la_row] = tb.x; Bs[0][la_q + 1][la_row] = tb.y;
    Bs[0][la_q + 2][la_row] = tb.z; Bs[0][la_q + 3][la_row] = tb.w;
    __syncthreads();

    const int KT = K / 16;
    int cur = 0;
    for (int kt = 0; kt < KT; kt++) {
        if (kt + 1 < KT) {
            ta = *(const float4*)(Ar + (kt + 1) * 16 + la_q);
            tb = *(const float4*)(Wr + (kt + 1) * 16 + la_q);
        }
        #pragma unroll
        for (int kk = 0; kk < 16; kk++) {
            float4 a = *(const float4*)&As[cur][kk][tr * 4];
            float4 b = *(const float4*)&Bs[cur][kk][tc * 4];
            float ra[4] = {a.x, a.y, a.z, a.w};
            float rb[4] = {b.x, b.y, b.z, b.w};
            #pragma unroll
            for (int i = 0; i < 4; i++)
                #pragma unroll
                for (int j = 0; j < 4; j++)
                    acc[i][j] += ra[i] * rb[j];
        }
        if (kt + 1 < KT) {
            int nb = cur ^ 1;
            As[nb][la_q + 0][la_row] = ta.x; As[nb][la_q + 1][la_row] = ta.y;
            As[nb][la_q + 2][la_row] = ta.z; As[nb][la_q + 3][la_row] = ta.w;
            Bs[nb][la_q + 0][la_row] = tb.x; Bs[nb][la_q + 1][la_row] = tb.y;
            Bs[nb][la_q + 2][la_row] = tb.z; Bs[nb][la_q + 3][la_row] = tb.w;
            __syncthreads();
            cur ^= 1;
        }
    }

    const int col = nBase + tc * 4;
    float4 bb = *(const float4*)(bias + col);
    float rb4[4] = {bb.x, bb.y, bb.z, bb.w};
    #pragma unroll
    for (int i = 0; i < 4; i++) {
        int m = mBase + tr * 4 + i;
        float4 v;
        v.x = alpha * (acc[i][0] + bScal * rb4[0]);
        v.y = alpha * (acc[i][1] + bScal * rb4[1]);
        v.z = alpha * (acc[i][2] + bScal * rb4[2]);
        v.w = alpha * (acc[i][3] + bScal * rb4[3]);
        *(float4*)(out + (long)m * E_DIM + col) = v;
    }
}

// ---------------------------------------------------------------------------
// Generic fp16 tensor-core GEMM (mma.sync.m16n8k16 + ldmatrix), 3-stage cp.async.
// CTA tile 128(M) x 256(N), 8 warps (2x4), warp tile 64x64, fp32 accum.
// EPI=2: out(half)  = fp16(acc), plain rows
// EPI=3: out(float) = acc + bias[(by>>1)*biasM + n], rows permuted rn->orig
// ---------------------------------------------------------------------------
#define HBK 32
#define HLDW 20
#define ASTG (128 * HLDW)
#define BSTG (256 * HLDW)
#define HNST 3
#define HSMEM_BYTES (HNST * (ASTG + BSTG) * 4)   // 92160

__device__ __forceinline__ void cp16(void* dst, const void* src) {
    uint32_t d = smem_u32(dst);
    asm volatile("cp.async.cg.shared.global [%0], [%1], 16;\n" :: "r"(d), "l"(src));
}

__device__ __forceinline__ void ldsm4(uint32_t* r, uint32_t addr) {
    asm volatile("ldmatrix.sync.aligned.m8n8.x4.shared.b16 {%0,%1,%2,%3}, [%4];"
                 : "=r"(r[0]), "=r"(r[1]), "=r"(r[2]), "=r"(r[3]) : "r"(addr));
}

__device__ __forceinline__ void mma16(float* d, const uint32_t* a, const uint32_t* b) {
    asm volatile(
        "mma.sync.aligned.m16n8k16.row.col.f32.f16.f16.f32 "
        "{%0,%1,%2,%3}, {%4,%5,%6,%7}, {%8,%9}, {%0,%1,%2,%3};"
        : "+f"(d[0]), "+f"(d[1]), "+f"(d[2]), "+f"(d[3])
        : "r"(a[0]), "r"(a[1]), "r"(a[2]), "r"(a[3]), "r"(b[0]), "r"(b[1]));
}

template<int EPI, typename OutT>
__global__ __launch_bounds__(256)
void hmma_gemm(const __half* __restrict__ A, int lda, size_t aZ,
               const __half* __restrict__ W, int ldb, size_t bZ, size_t bM,
               const float* __restrict__ bias, int biasM,
               OutT* __restrict__ out, int ldo, size_t oZ,
               int K)
{
    extern __shared__ uint32_t smw[];
    uint32_t* AsBase = smw;
    uint32_t* BsBase = smw + HNST * ASTG;

    const int tid  = threadIdx.x;
    const int w    = tid >> 5;
    const int lane = tid & 31;
    const int wm   = w >> 2;
    const int wn   = w & 3;
    const int lr   = lane >> 2;
    const int lc   = lane & 3;

    const __half* Ag = A + (size_t)blockIdx.y * 128 * lda + (size_t)blockIdx.z * aZ;
    const __half* Wg = W + (size_t)blockIdx.x * 256 * ldb + (size_t)blockIdx.z * bZ
                         + (size_t)(blockIdx.y >> 1) * bM;

    float acc[4][8][4];
    #pragma unroll
    for (int i = 0; i < 4; i++)
        #pragma unroll
        for (int j = 0; j < 8; j++)
            #pragma unroll
            for (int t = 0; t < 4; t++) acc[i][j][t] = 0.f;

    const int KT = K / HBK;

    const int lq = lane >> 3;
    const int l7 = lane & 7;
    const int aRowB = wm * 64 + (lq & 1) * 8 + l7;
    const int aColW = (lq >> 1) * 4;
    const int bRowB = wn * 64 + (lq >> 1) * 8 + l7;
    const int bColW = (lq & 1) * 4;

    #pragma unroll
    for (int s = 0; s < HNST - 1; s++) {
        if (s < KT) {
            #pragma unroll
            for (int l = 0; l < 2; l++) {
                int f = l * 256 + tid;
                int row = f >> 2, q = f & 3;
                cp16(&AsBase[s * ASTG + row * HLDW + q * 4],
                     Ag + (size_t)row * lda + s * HBK + q * 8);
            }
            #pragma unroll
            for (int l = 0; l < 4; l++) {
                int f = l * 256 + tid;
                int row = f >> 2, q = f & 3;
                cp16(&BsBase[s * BSTG + row * HLDW + q * 4],
                     Wg + (size_t)row * ldb + s * HBK + q * 8);
            }
        }
        asm volatile("cp.async.commit_group;\n");
    }

    int sc = 0, sl = HNST - 1;
    for (int kt = 0; kt < KT; kt++) {
        asm volatile("cp.async.wait_group %0;\n" :: "n"(HNST - 2) : "memory");
        __syncthreads();

        const uint32_t aByte = smem_u32(AsBase + sc * ASTG);
        const uint32_t bByte = smem_u32(BsBase + sc * BSTG);
        #pragma unroll
        for (int kc = 0; kc < 2; kc++) {
            uint32_t af[4][4], bf[8][2];
            #pragma unroll
            for (int i = 0; i < 4; i++)
                ldsm4(af[i], aByte + ((aRowB + i * 16) * HLDW + kc * 8 + aColW) * 4);
            #pragma unroll
            for (int jj = 0; jj < 4; jj++) {
                uint32_t r[4];
                ldsm4(r, bByte + ((bRowB + jj * 16) * HLDW + kc * 8 + bColW) * 4);
                bf[2 * jj][0] = r[0]; bf[2 * jj][1] = r[1];
                bf[2 * jj + 1][0] = r[2]; bf[2 * jj + 1][1] = r[3];
            }
            #pragma unroll
            for (int i = 0; i < 4; i++)
                #pragma unroll
                for (int j = 0; j < 8; j++)
                    mma16(acc[i][j], af[i], bf[j]);
        }

        const int ktNext = kt + HNST - 1;
        if (ktNext < KT) {
            #pragma unroll
            for (int l = 0; l < 2; l++) {
                int f = l * 256 + tid;
                int row = f >> 2, q = f & 3;
                cp16(&AsBase[sl * ASTG + row * HLDW + q * 4],
                     Ag + (size_t)row * lda + ktNext * HBK + q * 8);
            }
            #pragma unroll
            for (int l = 0; l < 4; l++) {
                int f = l * 256 + tid;
                int row = f >> 2, q = f & 3;
                cp16(&BsBase[sl * BSTG + row * HLDW + q * 4],
                     Wg + (size_t)row * ldb + ktNext * HBK + q * 8);
            }
        }
        asm volatile("cp.async.commit_group;\n");

        sc = (sc + 1 == HNST) ? 0 : sc + 1;
        sl = (sl + 1 == HNST) ? 0 : sl + 1;
    }

    const int mW = blockIdx.y * 128 + wm * 64;
    const int nW = blockIdx.x * 256 + wn * 64;
    const float* biasp = (EPI == 3) ? bias + (size_t)(blockIdx.y >> 1) * biasM : bias;
    OutT* outp = out + (size_t)blockIdx.z * oZ;

    #pragma unroll
    for (int i = 0; i < 4; i++) {
        int row0 = mW + i * 16 + lr;
        int row1 = row0 + 8;
        size_t or0, or1;
        if (EPI == 3) {
            int rn = row0 >> 8;
            int rbase = (rn >> 2) * 256, nb = rn & 3;
            or0 = ((size_t)(rbase + (row0 & 255))) * 4 + nb;
            or1 = ((size_t)(rbase + (row1 & 255))) * 4 + nb;
        } else {
            or0 = (size_t)row0; or1 = (size_t)row1;
        }
        #pragma unroll
        for (int j = 0; j < 8; j++) {
            int col = nW + j * 8 + lc * 2;
            if (EPI == 2) {
                __half2 h0 = __floats2half2_rn(acc[i][j][0], acc[i][j][1]);
                __half2 h1 = __floats2half2_rn(acc[i][j][2], acc[i][j][3]);
                *(__half2*)((__half*)outp + or0 * ldo + col) = h0;
                *(__half2*)((__half*)outp + or1 * ldo + col) = h1;
            } else {
                float b0 = biasp[col], b1 = biasp[col + 1];
                *(float2*)((float*)outp + or0 * ldo + col) =
                    make_float2(acc[i][j][0] + b0, acc[i][j][1] + b1);
                *(float2*)((float*)outp + or1 * ldo + col) =
                    make_float2(acc[i][j][2] + b0, acc[i][j][3] + b1);
            }
        }
    }
}

// ---------------------------------------------------------------------------
// Attention: d-outer/q-inner (16 independent accumulators) -> s[rn*H + h]
// ---------------------------------------------------------------------------
__global__ void attn_kernel(const float* __restrict__ qp,
                            const float* __restrict__ ksum,
                            float* __restrict__ sOut)
{
    const int h = blockIdx.x / B_DIM;
    const int n = blockIdx.x % B_DIM;
    const int qBase = blockIdx.y * 64;
    const int tid = threadIdx.x;

    __shared__ float ks[R_DIM][D_DIM + 1];
    __shared__ float qs[64][D_DIM + 1];

    for (int l = tid; l < 64 * 64; l += 256) {
        int r = l >> 6, d = l & 63;
        ks[r][d] = ksum[(r * B_DIM + n) * E_DIM + h * D_DIM + d];
        qs[r][d] = qp[((qBase + r) * B_DIM + n) * E_DIM + h * D_DIM + d];
    }
    __syncthreads();

    const int w = tid >> 5, lane = tid & 31;
    float d0[8], d1[8];
    #pragma unroll
    for (int qq = 0; qq < 8; qq++) { d0[qq] = 0.f; d1[qq] = 0.f; }

    #pragma unroll 4
    for (int d = 0; d < D_DIM; d++) {
        float k0 = ks[lane][d];
        float k1 = ks[lane + 32][d];
        #pragma unroll
        for (int qq = 0; qq < 8; qq++) {
            float qv = qs[w * 8 + qq][d];
            d0[qq] += qv * k0;
            d1[qq] += qv * k1;
        }
    }

    float acc0 = 0.f, acc1 = 0.f;
    #pragma unroll
    for (int qq = 0; qq < 8; qq++) {
        float mx = fmaxf(d0[qq], d1[qq]);
        #pragma unroll
        for (int o = 16; o; o >>= 1) mx = fmaxf(mx, __shfl_xor_sync(0xffffffffu, mx, o));
        float e0 = expf(d0[qq] - mx), e1 = expf(d1[qq] - mx);
        float sm = e0 + e1;
        #pragma unroll
        for (int o = 16; o; o >>= 1) sm += __shfl_xor_sync(0xffffffffu, sm, o);
        float inv = 1.f / sm;
        acc0 += e0 * inv;
        acc1 += e1 * inv;
    }
    atomicAdd(&sOut[(lane * B_DIM + n) * H_DIM + h], acc0);
    atomicAdd(&sOut[((lane + 32) * B_DIM + n) * H_DIM + h], acc1);
}

// ---------------------------------------------------------------------------
// Small prep kernels
// ---------------------------------------------------------------------------
__global__ void repack_kernel(const __half* __restrict__ K16, __half* __restrict__ KT)
{
    int ek = blockIdx.x * 256 + threadIdx.x;
    __half v[32];
    #pragma unroll
    for (int h = 0; h < H_DIM; h++)
        v[h] = K16[(size_t)h * EK + ek];
    #pragma unroll
    for (int h = H_DIM; h < 32; h++) v[h] = __ushort_as_half(0);
    uint4* d = (uint4*)(KT + (size_t)ek * 32);
    const uint4* s = (const uint4*)v;
    d[0] = s[0]; d[1] = s[1]; d[2] = s[2]; d[3] = s[3];
}

__global__ void fill_s16_kernel(const float* __restrict__ s, __half* __restrict__ s16)
{
    int i = blockIdx.x * 256 + threadIdx.x;
    int rn = i >> 5, h = i & 31;
    s16[i] = (h < H_DIM) ? __float2half_rn(s[rn * H_DIM + h]) : __ushort_as_half(0);
}

__global__ void pb_kernel(const float* __restrict__ Wo, const float* __restrict__ bv,
                          float* __restrict__ pb)
{
    int h = blockIdx.x;
    int e = blockIdx.y * 128 + threadIdx.x;
    const float* wrow = Wo + (size_t)e * E_DIM + h * D_DIM;
    const float* b = bv + h * D_DIM;
    float a = 0.f;
    #pragma unroll
    for (int d = 0; d < D_DIM; d++) a += b[d] * wrow[d];
    pb[h * E_DIM + e] = a;
}

__global__ void qbias_kernel(const float* __restrict__ s, const float* __restrict__ pb,
                             const float* __restrict__ bo, float* __restrict__ q)
{
    int rn = blockIdx.x;
    int e = blockIdx.y * 256 + threadIdx.x;
    float a = bo[e];
    #pragma unroll
    for (int h = 0; h < H_DIM; h++)
        a += s[rn * H_DIM + h] * pb[h * E_DIM + e];
    q[rn * E_DIM + e] = a;
}

// ---------------------------------------------------------------------------
// Launch
// ---------------------------------------------------------------------------
extern "C" void kernel_launch(void* const* d_in, const int* in_sizes, int n_in,
                              void* d_out, int out_size)
{
    const float* x     = (const float*)d_in[0];
    const float* query = (const float*)d_in[1];
    const float* Wq    = (const float*)d_in[2];
    const float* bq    = (const float*)d_in[3];
    const float* Wk    = (const float*)d_in[4];
    const float* bk    = (const float*)d_in[5];
    const float* Wv    = (const float*)d_in[6];
    const float* bv    = (const float*)d_in[7];
    const float* Wo    = (const float*)d_in[8];
    const float* bo    = (const float*)d_in[9];
    float* out = (float*)d_out;

    void *p;
    cudaGetSymbolAddress(&p, g_xsum);  float*  xsum = (float*)p;
    cudaGetSymbolAddress(&p, g_qp);    float*  qp   = (float*)p;
    cudaGetSymbolAddress(&p, g_ksum);  float*  ksum = (float*)p;
    cudaGetSymbolAddress(&p, g_s);     float*  sArr = (float*)p;
    cudaGetSymbolAddress(&p, g_x16p);  __half* x16p = (__half*)p;
    cudaGetSymbolAddress(&p, g_hWo);   __half* hWo  = (__half*)p;
    cudaGetSymbolAddress(&p, g_hWvT);  __half* hWvT = (__half*)p;
    cudaGetSymbolAddress(&p, g_K16);   __half* K16  = (__half*)p;
    cudaGetSymbolAddress(&p, g_KT);    __half* KT   = (__half*)p;
    cudaGetSymbolAddress(&p, g_s16);   __half* s16  = (__half*)p;
    cudaGetSymbolAddress(&p, g_pb);    float*  pb   = (float*)p;
    cudaGetSymbolAddress(&p, g_q);     float*  q    = (float*)p;
    cudaGetSymbolAddress(&p, g_M);     __half* M    = (__half*)p;

    cudaFuncSetAttribute(hmma_gemm<2, __half>,
                         cudaFuncAttributeMaxDynamicSharedMemorySize, HSMEM_BYTES);
    cudaFuncSetAttribute(hmma_gemm<3, float>,
                         cudaFuncAttributeMaxDynamicSharedMemorySize, HSMEM_BYTES);

    const float scaling = (1.0f / 8.0f) / 16.0f;   // D^-0.5 / sqrt(Q)

    cudaMemsetAsync(sArr, 0, RN_CNT * H_DIM * sizeof(float));

    // 1) column-sum of x + fp16 permuted copy (float4 over e)
    xsum_kernel<<<(RN_CNT * 192) / 256, 256>>>(x, xsum, x16p);

    // 2) weight conversions
    convw_kernel<<<dim3(24, 24), dim3(32, 8)>>>(Wv, Wo, hWvT, hWo);

    // 3) merged projections: qp (blocks 0..191) + ksum (blocks 192..239)
    proj_kernel<<<240, 256>>>(query, Wq, bq, qp, xsum, Wk, bk, ksum, scaling);

    // 4) attention -> s[rn,h]
    attn_kernel<<<dim3(H_DIM * B_DIM, Q_DIM / 64), 256>>>(qp, ksum, sArr);

    // 5) K_h[e,k] = Wo[:,hblk] @ Wv[hblk,:]  (fp16 out), z = head
    hmma_gemm<2, __half><<<dim3(E_DIM / 256, E_DIM / 128, H_DIM), 256, HSMEM_BYTES>>>(
        hWo, E_DIM, (size_t)D_DIM,
        hWvT, E_DIM, (size_t)D_DIM, 0,
        nullptr, 0,
        K16, E_DIM, (size_t)EK,
        D_DIM);

    // 6) repack K16 -> KT[ek][h] (padded to 32)
    repack_kernel<<<EK / 256, 256>>>(K16, KT);

    // 7) s -> fp16 padded
    fill_s16_kernel<<<(RN_CNT * 32) / 256, 256>>>(sArr, s16);

    // 8) bias precompute
    pb_kernel<<<dim3(H_DIM, E_DIM / 128), 128>>>(Wo, bv, pb);
    qbias_kernel<<<dim3(RN_CNT, E_DIM / 256), 256>>>(sArr, pb, bo, q);

    // 9) M[rn, ek] = sum_h s16[rn,h] * KT[ek,h]
    hmma_gemm<2, __half><<<dim3(EK / 256, RN_CNT / 128), 256, HSMEM_BYTES>>>(
        s16, 32, 0,
        KT, 32, 0, 0,
        nullptr, 0,
        M, EK, 0,
        32);

    // 10) out = x16p @ M_rn^T + q_rn  (rows permuted back to [r,c,n])
    hmma_gemm<3, float><<<dim3(E_DIM / 256, M_BIG / 128), 256, HSMEM_BYTES>>>(
        x16p, E_DIM, 0,
        M, E_DIM, 0, (size_t)EK,
        q, E_DIM,
        out, E_DIM, 0,
        E_DIM);
}